// round 10
// baseline (speedup 1.0000x reference)
#include <cuda_runtime.h>
#include <math.h>
#include <stdint.h>

#define B_  2
#define T_  2048
#define C_  2048
#define H_  16
#define KV_ 4
#define D_  128
#define REP_ 4
#define KDIM 2048

// Scratch (allocation-free rule: __device__ globals)
__device__ float g_q[B_ * H_ * T_ * D_];     // [B,H,T,D] q (pre/post rope)
__device__ float g_attn[B_ * T_ * H_ * D_];  // [B,T,H*D] attention output rows

// ---------------------------------------------------------------------------
// tf32 helpers
// ---------------------------------------------------------------------------
__device__ __forceinline__ uint32_t f2tf32(float f) {
    uint32_t u;
    asm("cvt.rna.tf32.f32 %0, %1;" : "=r"(u) : "f"(f));
    return u;
}

__device__ __forceinline__ void mma_tf32(float c[4],
                                         uint32_t a0, uint32_t a1, uint32_t a2, uint32_t a3,
                                         uint32_t b0, uint32_t b1) {
    asm volatile(
        "mma.sync.aligned.m16n8k8.row.col.f32.tf32.tf32.f32 "
        "{%0,%1,%2,%3}, {%4,%5,%6,%7}, {%8,%9}, {%0,%1,%2,%3};"
        : "+f"(c[0]), "+f"(c[1]), "+f"(c[2]), "+f"(c[3])
        : "r"(a0), "r"(a1), "r"(a2), "r"(a3), "r"(b0), "r"(b1));
}

// ---------------------------------------------------------------------------
// tf32 GEMM, 64x64 warp tiles (proven r9): out = A[M,2048] @ W[2048,N] (+bias)
// ---------------------------------------------------------------------------
#define SA 20
#define SB 136

__device__ __forceinline__ void gemm_body(
    const float* __restrict__ A, const float* __restrict__ W,
    const float* __restrict__ bias, float* __restrict__ out,
    int N, int mode, int m0, int n0)
{
    __shared__ uint32_t As[128 * SA];
    __shared__ uint32_t Bs[16 * SB];

    const int tid  = threadIdx.x;          // 0..127
    const int wid  = tid >> 5;             // 0..3
    const int lane = tid & 31;
    const int g = lane >> 2;
    const int t = lane & 3;
    const int warp_m = (wid & 1) * 64;
    const int warp_n = (wid >> 1) * 64;

    float acc[4][8][4];
#pragma unroll
    for (int mt = 0; mt < 4; mt++)
#pragma unroll
        for (int nt = 0; nt < 8; nt++)
#pragma unroll
            for (int i = 0; i < 4; i++) acc[mt][nt][i] = 0.0f;

    const int aRow = tid >> 2;
    const int aCol = (tid & 3) * 4;
    const int bRow = tid >> 5;
    const int bCol = (tid & 31) * 4;

    const float* pa = A + (size_t)(m0 + aRow) * KDIM + aCol;
    const float* pb = W + (size_t)bRow * N + n0 + bCol;

    float4 av[4], bv[4];
#pragma unroll
    for (int c = 0; c < 4; c++) {
        av[c] = *(const float4*)(pa + (size_t)(32 * c) * KDIM);
        bv[c] = *(const float4*)(pb + (size_t)(4 * c) * N);
    }

    for (int k0 = 0; k0 < KDIM; k0 += 16) {
        __syncthreads();
#pragma unroll
        for (int c = 0; c < 4; c++) {
            uint32_t* qa = &As[(aRow + 32 * c) * SA + aCol];
            qa[0] = f2tf32(av[c].x); qa[1] = f2tf32(av[c].y);
            qa[2] = f2tf32(av[c].z); qa[3] = f2tf32(av[c].w);
            uint32_t* qb = &Bs[(bRow + 4 * c) * SB + bCol];
            qb[0] = f2tf32(bv[c].x); qb[1] = f2tf32(bv[c].y);
            qb[2] = f2tf32(bv[c].z); qb[3] = f2tf32(bv[c].w);
        }
        __syncthreads();

        if (k0 + 16 < KDIM) {
            pa += 16;
            pb += (size_t)16 * N;
#pragma unroll
            for (int c = 0; c < 4; c++) {
                av[c] = *(const float4*)(pa + (size_t)(32 * c) * KDIM);
                bv[c] = *(const float4*)(pb + (size_t)(4 * c) * N);
            }
        }

#pragma unroll
        for (int kk = 0; kk < 16; kk += 8) {
            uint32_t afr[4][4];
#pragma unroll
            for (int mt = 0; mt < 4; mt++) {
                const int rb = warp_m + mt * 16;
                afr[mt][0] = As[(rb + g)     * SA + kk + t];
                afr[mt][1] = As[(rb + g + 8) * SA + kk + t];
                afr[mt][2] = As[(rb + g)     * SA + kk + t + 4];
                afr[mt][3] = As[(rb + g + 8) * SA + kk + t + 4];
            }
            uint32_t bfr[8][2];
#pragma unroll
            for (int nt = 0; nt < 8; nt++) {
                const int cn = warp_n + nt * 8 + g;
                bfr[nt][0] = Bs[(kk + t)     * SB + cn];
                bfr[nt][1] = Bs[(kk + t + 4) * SB + cn];
            }
#pragma unroll
            for (int mt = 0; mt < 4; mt++)
#pragma unroll
                for (int nt = 0; nt < 8; nt++)
                    mma_tf32(acc[mt][nt],
                             afr[mt][0], afr[mt][1], afr[mt][2], afr[mt][3],
                             bfr[nt][0], bfr[nt][1]);
        }
    }

#pragma unroll
    for (int mt = 0; mt < 4; mt++) {
#pragma unroll
        for (int nt = 0; nt < 8; nt++) {
            const int col = n0 + warp_n + nt * 8 + 2 * t;
            float bx = 0.0f, by = 0.0f;
            if (bias) { bx = bias[col]; by = bias[col + 1]; }
#pragma unroll
            for (int half = 0; half < 2; half++) {
                const int m = m0 + warp_m + mt * 16 + g + half * 8;
                float2 r;
                r.x = acc[mt][nt][half * 2 + 0] + bx;
                r.y = acc[mt][nt][half * 2 + 1] + by;
                if (mode == 0) {
                    *(float2*)&out[(size_t)m * N + col] = r;
                } else {
                    const int b  = m >> 11;
                    const int tt = m & (T_ - 1);
                    const int h  = col >> 7;
                    const int dd = col & 127;
                    *(float2*)&out[((size_t)(b * (N >> 7) + h) * T_ + tt) * D_ + dd] = r;
                }
            }
        }
    }
}

__global__ __launch_bounds__(128, 2) void qkv_gemm(
    const float* __restrict__ x,
    const float* __restrict__ wq, const float* __restrict__ bq,
    const float* __restrict__ wk, const float* __restrict__ bk,
    const float* __restrict__ wv, const float* __restrict__ bv,
    float* __restrict__ out_k, float* __restrict__ out_v)
{
    const int bx = blockIdx.x;
    const float* W; const float* bias; float* out; int N; int n0;
    if (bx < 16)      { W = wq; bias = bq; out = (float*)g_q; N = 2048; n0 = bx * 128; }
    else if (bx < 20) { W = wk; bias = bk; out = out_k; N = 512; n0 = (bx - 16) * 128; }
    else              { W = wv; bias = bv; out = out_v; N = 512; n0 = (bx - 20) * 128; }
    gemm_body(x, W, bias, out, N, 1, blockIdx.y * 128, n0);
}

__global__ __launch_bounds__(128, 2) void oproj_gemm(
    const float* __restrict__ wo, float* __restrict__ out)
{
    gemm_body((const float*)g_attn, wo, nullptr, out, 2048, 0,
              blockIdx.y * 128, blockIdx.x * 128);
}

// ---------------------------------------------------------------------------
// RoPE in place, fused q (g_q) + k (out_k): pair (j, j+64)
// ---------------------------------------------------------------------------
#define PQ (B_ * H_ * T_ * 64)
#define PK (B_ * KV_ * T_ * 64)

__global__ void rope_all(float* __restrict__ out_k)
{
    int idx = blockIdx.x * blockDim.x + threadIdx.x;
    float* x;
    if (idx < PQ) { x = (float*)g_q; }
    else          { x = out_k; idx -= PQ; if (idx >= PK) return; }

    const int j = idx & 63;
    const int t = (idx >> 6) & (T_ - 1);
    const int bh = idx >> 17;

    const float freq = expf(-13.815510557964274f * ((float)j / 64.0f));
    const float theta = (float)t * freq;
    const float s = sinf(theta);
    const float c = cosf(theta);

    float* base = x + ((size_t)bh * T_ + t) * D_;
    const float v1 = base[j];
    const float v2 = base[j + 64];
    base[j]      = c * v1 - s * v2;
    base[j + 64] = c * v2 + s * v1;
}

// ---------------------------------------------------------------------------
// Flash attention, tf32 MMA, DOUBLE-BUFFERED K/V fragment staging.
// Q tile 128 rows, KV tile 64 rows, 8 warps x 16 q-rows.
// Per iteration: LDG(next) -> compute(cur buf) -> cvt+STS(next buf) -> sync.
// smem words: Qf 16384 | KV buf0 16384 (Kf+Vf) | KV buf1 16384 | Pf 8192
// = 57344 words = 229376 B (fits 232448 cap, occupancy 1 as before).
// ---------------------------------------------------------------------------
#define QF_OFF  0
#define KV_OFF  16384
#define PF_OFF  49152
#define FL_SMEM_BYTES (57344 * 4)

__global__ __launch_bounds__(256, 1) void flash_mma(
    const float* __restrict__ k, const float* __restrict__ v)
{
    extern __shared__ uint32_t sm[];
    uint32_t* Qf = sm + QF_OFF;
    uint32_t* Pf = sm + PF_OFF;

    const int tid = threadIdx.x;
    const int lane = tid & 31;
    const int wid = tid >> 5;
    const int g = lane >> 2;
    const int t = lane & 3;

    const int q0 = (int)(gridDim.x - 1 - blockIdx.x) * 128;  // heavy tiles first
    const int h  = blockIdx.y;
    const int b  = blockIdx.z;
    const int kvh = h >> 2;

    const float* qp = (const float*)g_q + ((size_t)(b * H_ + h) * T_ + q0) * D_;
    const float* kp = k + ((size_t)(b * KV_ + kvh) * T_) * D_;
    const float* vp = v + ((size_t)(b * KV_ + kvh) * T_) * D_;

    // ---- load Q tile into fragment layout ----
    {
        const int mrow  = tid >> 1;
        const int dbase = (tid & 1) * 64;
        const int stripe = mrow >> 4;
        const int r  = mrow & 15;
        const int gg = r & 7;
        const int i0 = r >> 3;
        const float* qrow = qp + (size_t)mrow * D_;
#pragma unroll
        for (int it = 0; it < 16; it++) {
            const int d0 = dbase + it * 4;
            float4 q4 = *(const float4*)(qrow + d0);
            float vals[4] = {q4.x, q4.y, q4.z, q4.w};
#pragma unroll
            for (int j = 0; j < 4; j++) {
                const int dd = d0 + j;
                const int c = dd >> 3, u = dd & 7;
                Qf[(((stripe * 16 + c) * 32) + gg * 4 + (u & 3)) * 4 +
                   (i0 | ((u >> 2) << 1))] = f2tf32(vals[j]);
            }
        }
    }

    float acc_o[16][4];
#pragma unroll
    for (int nt = 0; nt < 16; nt++)
#pragma unroll
        for (int i = 0; i < 4; i++) acc_o[nt][i] = 0.0f;

    float m0 = -INFINITY, m1 = -INFINITY, l0 = 0.0f, l1 = 0.0f;
    const float scale = 0.08838834764831845f;  // 1/sqrt(128)

    const int r0 = q0 + wid * 16 + g;
    const int r1 = r0 + 8;
    const int warp_last = q0 + wid * 16 + 15;
    const int ntiles = q0 / 64 + 2;

    // K/V loader index precompute
    const int srow = tid >> 2;            // 0..63
    const int dbv  = (tid & 3) * 32;
    const int ntk = srow >> 3;
    const int gk  = srow & 7;
    const int csV = srow >> 3;
    const int usV = srow & 7;
    const int tsV = usV & 3;
    const int hsV = usV >> 2;

    float4 pk[8], pv[8];

    // fill helper: convert regs -> fragment buffers
    auto kv_fill = [&](uint32_t* Kf, uint32_t* Vf) {
#pragma unroll
        for (int it = 0; it < 8; it++) {
            float kv4[4] = {pk[it].x, pk[it].y, pk[it].z, pk[it].w};
            float vv4[4] = {pv[it].x, pv[it].y, pv[it].z, pv[it].w};
#pragma unroll
            for (int j = 0; j < 4; j++) {
                const int dd = dbv + it * 4 + j;
                const int ck = dd >> 3, uk = dd & 7;
                Kf[((ntk * 16 + ck) * 32 + gk * 4 + (uk & 3)) * 2 + (uk >> 2)] =
                    f2tf32(kv4[j]);
                Vf[(((dd >> 3) * 8 + csV) * 32 + (dd & 7) * 4 + tsV) * 2 + hsV] =
                    f2tf32(vv4[j]);
            }
        }
    };

    // ---- prologue: stage tile 0 into buffer 0 ----
    {
        const float* krow = kp + (size_t)srow * D_;
        const float* vrow = vp + (size_t)srow * D_;
#pragma unroll
        for (int it = 0; it < 8; it++) {
            pk[it] = *(const float4*)(krow + dbv + it * 4);
            pv[it] = *(const float4*)(vrow + dbv + it * 4);
        }
    }
    kv_fill(sm + KV_OFF, sm + KV_OFF + 8192);
    __syncthreads();

    for (int ti = 0; ti < ntiles; ti++) {
        const int s0 = ti * 64;
        uint32_t* Kf = sm + KV_OFF + (ti & 1) * 16384;
        uint32_t* Vf = Kf + 8192;

        // prefetch next tile's K/V into registers (latency hides behind MMAs)
        const bool have_next = (ti + 1 < ntiles);
        if (have_next) {
            const float* krow = kp + (size_t)((ti + 1) * 64 + srow) * D_;
            const float* vrow = vp + (size_t)((ti + 1) * 64 + srow) * D_;
#pragma unroll
            for (int it = 0; it < 8; it++) {
                pk[it] = *(const float4*)(krow + dbv + it * 4);
                pv[it] = *(const float4*)(vrow + dbv + it * 4);
            }
        }

        if (s0 <= warp_last) {
            // ---- S = Q @ K^T ----
            float accs[8][4];
#pragma unroll
            for (int nt = 0; nt < 8; nt++)
#pragma unroll
                for (int i = 0; i < 4; i++) accs[nt][i] = 0.0f;

#pragma unroll
            for (int c = 0; c < 16; c++) {
                uint4 a = *(const uint4*)&Qf[((wid * 16 + c) * 32 + lane) * 4];
#pragma unroll
                for (int nt = 0; nt < 8; nt++) {
                    uint2 bb = *(const uint2*)&Kf[((nt * 16 + c) * 32 + lane) * 2];
                    mma_tf32(accs[nt], a.x, a.y, a.z, a.w, bb.x, bb.y);
                }
            }

            // ---- online softmax ----
            float mx0 = -INFINITY, mx1 = -INFINITY;
#pragma unroll
            for (int nt = 0; nt < 8; nt++) {
                const int c0 = s0 + nt * 8 + 2 * t;
                accs[nt][0] = (c0     <= r0) ? accs[nt][0] * scale : -INFINITY;
                accs[nt][1] = (c0 + 1 <= r0) ? accs[nt][1] * scale : -INFINITY;
                accs[nt][2] = (c0     <= r1) ? accs[nt][2] * scale : -INFINITY;
                accs[nt][3] = (c0 + 1 <= r1) ? accs[nt][3] * scale : -INFINITY;
                mx0 = fmaxf(mx0, fmaxf(accs[nt][0], accs[nt][1]));
                mx1 = fmaxf(mx1, fmaxf(accs[nt][2], accs[nt][3]));
            }
            mx0 = fmaxf(mx0, __shfl_xor_sync(0xffffffffu, mx0, 1));
            mx0 = fmaxf(mx0, __shfl_xor_sync(0xffffffffu, mx0, 2));
            mx1 = fmaxf(mx1, __shfl_xor_sync(0xffffffffu, mx1, 1));
            mx1 = fmaxf(mx1, __shfl_xor_sync(0xffffffffu, mx1, 2));

            const float mn0 = fmaxf(m0, mx0);
            const float mn1 = fmaxf(m1, mx1);
            const float corr0 = __expf(m0 - mn0);
            const float corr1 = __expf(m1 - mn1);
            m0 = mn0; m1 = mn1;

            float s0s = 0.0f, s1s = 0.0f;
#pragma unroll
            for (int nt = 0; nt < 8; nt++) {
                accs[nt][0] = __expf(accs[nt][0] - mn0);
                accs[nt][1] = __expf(accs[nt][1] - mn0);
                accs[nt][2] = __expf(accs[nt][2] - mn1);
                accs[nt][3] = __expf(accs[nt][3] - mn1);
                s0s += accs[nt][0] + accs[nt][1];
                s1s += accs[nt][2] + accs[nt][3];
            }
            s0s += __shfl_xor_sync(0xffffffffu, s0s, 1);
            s0s += __shfl_xor_sync(0xffffffffu, s0s, 2);
            s1s += __shfl_xor_sync(0xffffffffu, s1s, 1);
            s1s += __shfl_xor_sync(0xffffffffu, s1s, 2);
            l0 = l0 * corr0 + s0s;
            l1 = l1 * corr1 + s1s;

#pragma unroll
            for (int nt = 0; nt < 16; nt++) {
                acc_o[nt][0] *= corr0; acc_o[nt][1] *= corr0;
                acc_o[nt][2] *= corr1; acc_o[nt][3] *= corr1;
            }

            // ---- P into fragment layout (warp-local) ----
            __syncwarp();
#pragma unroll
            for (int nt = 0; nt < 8; nt++) {
                const int u0 = 2 * t, u1 = 2 * t + 1;
                const int base = (wid * 8 + nt) * 32 + g * 4;
                Pf[(base + (u0 & 3)) * 4 + ((u0 >> 2) << 1) + 0] = f2tf32(accs[nt][0]);
                Pf[(base + (u0 & 3)) * 4 + ((u0 >> 2) << 1) + 1] = f2tf32(accs[nt][2]);
                Pf[(base + (u1 & 3)) * 4 + ((u1 >> 2) << 1) + 0] = f2tf32(accs[nt][1]);
                Pf[(base + (u1 & 3)) * 4 + ((u1 >> 2) << 1) + 1] = f2tf32(accs[nt][3]);
            }
            __syncwarp();

            // ---- O += P @ V ----
#pragma unroll
            for (int c = 0; c < 8; c++) {
                uint4 a = *(const uint4*)&Pf[((wid * 8 + c) * 32 + lane) * 4];
#pragma unroll
                for (int nt = 0; nt < 16; nt++) {
                    uint2 bb = *(const uint2*)&Vf[((nt * 8 + c) * 32 + lane) * 2];
                    mma_tf32(acc_o[nt], a.x, a.y, a.z, a.w, bb.x, bb.y);
                }
            }
        }

        // stage next tile into the other buffer
        if (have_next) {
            uint32_t* Kn = sm + KV_OFF + ((ti + 1) & 1) * 16384;
            kv_fill(Kn, Kn + 8192);
        }
        __syncthreads();
    }

    // ---- epilogue: normalize + write [B,T,H*D] ----
    const float inv0 = 1.0f / l0;
    const float inv1 = 1.0f / l1;
    float* o = (float*)g_attn;
    const size_t ro0 = ((size_t)(b * T_ + r0)) * C_ + h * D_;
    const size_t ro1 = ((size_t)(b * T_ + r1)) * C_ + h * D_;
#pragma unroll
    for (int nt = 0; nt < 16; nt++) {
        const int col = nt * 8 + 2 * t;
        float2 w0, w1;
        w0.x = acc_o[nt][0] * inv0; w0.y = acc_o[nt][1] * inv0;
        w1.x = acc_o[nt][2] * inv1; w1.y = acc_o[nt][3] * inv1;
        *(float2*)&o[ro0 + col] = w0;
        *(float2*)&o[ro1 + col] = w1;
    }
}

// ---------------------------------------------------------------------------
extern "C" void kernel_launch(void* const* d_in, const int* in_sizes, int n_in,
                              void* d_out, int out_size)
{
    const float* x  = (const float*)d_in[0];
    const float* wq = (const float*)d_in[1];
    const float* bq = (const float*)d_in[2];
    const float* wk = (const float*)d_in[3];
    const float* bk = (const float*)d_in[4];
    const float* wv = (const float*)d_in[5];
    const float* bv = (const float*)d_in[6];
    const float* wo = (const float*)d_in[7];

    float* out_main = (float*)d_out;                    // [B,T,C]
    float* out_k = out_main + (size_t)B_ * T_ * C_;     // [B,KV,T,D]
    float* out_v = out_k + (size_t)B_ * KV_ * T_ * D_;  // [B,KV,T,D]

    const int M = B_ * T_;  // 4096

    // Fused QKV projection
    {
        dim3 g(24, M / 128);
        qkv_gemm<<<g, 128>>>(x, wq, bq, wk, bk, wv, bv, out_k, out_v);
    }

    // RoPE on q (g_q) and k (out_k), fused single launch
    {
        const int total = PQ + PK;
        rope_all<<<(total + 255) / 256, 256>>>(out_k);
    }

    // Flash attention (tf32 MMA, double-buffered K/V staging)
    {
        cudaFuncSetAttribute(flash_mma,
                             cudaFuncAttributeMaxDynamicSharedMemorySize,
                             FL_SMEM_BYTES);
        dim3 g(T_ / 128, H_, B_);
        flash_mma<<<g, 256, FL_SMEM_BYTES>>>(out_k, out_v);
    }

    // Output projection
    {
        dim3 go(C_ / 128, M / 128);
        oproj_gemm<<<go, 128>>>(wo, out_main);
    }
}

// round 11
// speedup vs baseline: 1.0825x; 1.0825x over previous
#include <cuda_runtime.h>
#include <math.h>
#include <stdint.h>

#define B_  2
#define T_  2048
#define C_  2048
#define H_  16
#define KV_ 4
#define D_  128
#define REP_ 4
#define KDIM 2048

// Scratch (allocation-free rule: __device__ globals)
__device__ float g_q[B_ * H_ * T_ * D_];     // [B,H,T,D] q (pre/post rope)
__device__ float g_attn[B_ * T_ * H_ * D_];  // [B,T,H*D] attention output rows

// ---------------------------------------------------------------------------
// tf32 helpers
// ---------------------------------------------------------------------------
__device__ __forceinline__ uint32_t f2tf32(float f) {
    uint32_t u;
    asm("cvt.rna.tf32.f32 %0, %1;" : "=r"(u) : "f"(f));
    return u;
}

__device__ __forceinline__ void mma_tf32(float c[4],
                                         uint32_t a0, uint32_t a1, uint32_t a2, uint32_t a3,
                                         uint32_t b0, uint32_t b1) {
    asm volatile(
        "mma.sync.aligned.m16n8k8.row.col.f32.tf32.tf32.f32 "
        "{%0,%1,%2,%3}, {%4,%5,%6,%7}, {%8,%9}, {%0,%1,%2,%3};"
        : "+f"(c[0]), "+f"(c[1]), "+f"(c[2]), "+f"(c[3])
        : "r"(a0), "r"(a1), "r"(a2), "r"(a3), "r"(b0), "r"(b1));
}

// ---------------------------------------------------------------------------
// tf32 GEMM, 64x64 warp tiles, SMEM PING-PONG mainloop:
// per slab: LDG(next) -> MMA(cur buf) -> STS(next -> other buf) -> 1 sync.
// ---------------------------------------------------------------------------
#define SA 20
#define SB 136

__device__ __forceinline__ void gemm_body(
    const float* __restrict__ A, const float* __restrict__ W,
    const float* __restrict__ bias, float* __restrict__ out,
    int N, int mode, int m0, int n0)
{
    __shared__ uint32_t As[2][128 * SA];
    __shared__ uint32_t Bs[2][16 * SB];

    const int tid  = threadIdx.x;          // 0..127
    const int wid  = tid >> 5;             // 0..3
    const int lane = tid & 31;
    const int g = lane >> 2;
    const int t = lane & 3;
    const int warp_m = (wid & 1) * 64;
    const int warp_n = (wid >> 1) * 64;

    float acc[4][8][4];
#pragma unroll
    for (int mt = 0; mt < 4; mt++)
#pragma unroll
        for (int nt = 0; nt < 8; nt++)
#pragma unroll
            for (int i = 0; i < 4; i++) acc[mt][nt][i] = 0.0f;

    const int aRow = tid >> 2;             // 0..31
    const int aCol = (tid & 3) * 4;
    const int bRow = tid >> 5;             // 0..3
    const int bCol = (tid & 31) * 4;

    const float* pa = A + (size_t)(m0 + aRow) * KDIM + aCol;
    const float* pb = W + (size_t)bRow * N + n0 + bCol;

    float4 av[4], bv[4];
#pragma unroll
    for (int c = 0; c < 4; c++) {
        av[c] = *(const float4*)(pa + (size_t)(32 * c) * KDIM);
        bv[c] = *(const float4*)(pb + (size_t)(4 * c) * N);
    }

    // prologue: stage slab 0 into buffer 0
#pragma unroll
    for (int c = 0; c < 4; c++) {
        uint32_t* qa = &As[0][(aRow + 32 * c) * SA + aCol];
        qa[0] = f2tf32(av[c].x); qa[1] = f2tf32(av[c].y);
        qa[2] = f2tf32(av[c].z); qa[3] = f2tf32(av[c].w);
        uint32_t* qb = &Bs[0][(bRow + 4 * c) * SB + bCol];
        qb[0] = f2tf32(bv[c].x); qb[1] = f2tf32(bv[c].y);
        qb[2] = f2tf32(bv[c].z); qb[3] = f2tf32(bv[c].w);
    }
    __syncthreads();

    for (int k0 = 0; k0 < KDIM; k0 += 16) {
        const int cur = (k0 >> 4) & 1;
        const bool have_next = (k0 + 16 < KDIM);

        // LDG next slab (latency hidden behind MMAs below)
        if (have_next) {
            pa += 16;
            pb += (size_t)16 * N;
#pragma unroll
            for (int c = 0; c < 4; c++) {
                av[c] = *(const float4*)(pa + (size_t)(32 * c) * KDIM);
                bv[c] = *(const float4*)(pb + (size_t)(4 * c) * N);
            }
        }

        // MMA on current buffer
#pragma unroll
        for (int kk = 0; kk < 16; kk += 8) {
            uint32_t afr[4][4];
#pragma unroll
            for (int mt = 0; mt < 4; mt++) {
                const int rb = warp_m + mt * 16;
                afr[mt][0] = As[cur][(rb + g)     * SA + kk + t];
                afr[mt][1] = As[cur][(rb + g + 8) * SA + kk + t];
                afr[mt][2] = As[cur][(rb + g)     * SA + kk + t + 4];
                afr[mt][3] = As[cur][(rb + g + 8) * SA + kk + t + 4];
            }
            uint32_t bfr[8][2];
#pragma unroll
            for (int nt = 0; nt < 8; nt++) {
                const int cn = warp_n + nt * 8 + g;
                bfr[nt][0] = Bs[cur][(kk + t)     * SB + cn];
                bfr[nt][1] = Bs[cur][(kk + t + 4) * SB + cn];
            }
#pragma unroll
            for (int mt = 0; mt < 4; mt++)
#pragma unroll
                for (int nt = 0; nt < 8; nt++)
                    mma_tf32(acc[mt][nt],
                             afr[mt][0], afr[mt][1], afr[mt][2], afr[mt][3],
                             bfr[nt][0], bfr[nt][1]);
        }

        // STS next slab into the other buffer
        if (have_next) {
            const int nxt = cur ^ 1;
#pragma unroll
            for (int c = 0; c < 4; c++) {
                uint32_t* qa = &As[nxt][(aRow + 32 * c) * SA + aCol];
                qa[0] = f2tf32(av[c].x); qa[1] = f2tf32(av[c].y);
                qa[2] = f2tf32(av[c].z); qa[3] = f2tf32(av[c].w);
                uint32_t* qb = &Bs[nxt][(bRow + 4 * c) * SB + bCol];
                qb[0] = f2tf32(bv[c].x); qb[1] = f2tf32(bv[c].y);
                qb[2] = f2tf32(bv[c].z); qb[3] = f2tf32(bv[c].w);
            }
        }
        __syncthreads();
    }

#pragma unroll
    for (int mt = 0; mt < 4; mt++) {
#pragma unroll
        for (int nt = 0; nt < 8; nt++) {
            const int col = n0 + warp_n + nt * 8 + 2 * t;
            float bx = 0.0f, by = 0.0f;
            if (bias) { bx = bias[col]; by = bias[col + 1]; }
#pragma unroll
            for (int half = 0; half < 2; half++) {
                const int m = m0 + warp_m + mt * 16 + g + half * 8;
                float2 r;
                r.x = acc[mt][nt][half * 2 + 0] + bx;
                r.y = acc[mt][nt][half * 2 + 1] + by;
                if (mode == 0) {
                    *(float2*)&out[(size_t)m * N + col] = r;
                } else {
                    const int b  = m >> 11;
                    const int tt = m & (T_ - 1);
                    const int h  = col >> 7;
                    const int dd = col & 127;
                    *(float2*)&out[((size_t)(b * (N >> 7) + h) * T_ + tt) * D_ + dd] = r;
                }
            }
        }
    }
}

// Fused QKV: grid.x = 24 (0..15 Q tiles, 16..19 K tiles, 20..23 V tiles)
__global__ __launch_bounds__(128, 2) void qkv_gemm(
    const float* __restrict__ x,
    const float* __restrict__ wq, const float* __restrict__ bq,
    const float* __restrict__ wk, const float* __restrict__ bk,
    const float* __restrict__ wv, const float* __restrict__ bv,
    float* __restrict__ out_k, float* __restrict__ out_v)
{
    const int bx = blockIdx.x;
    const float* W; const float* bias; float* out; int N; int n0;
    if (bx < 16)      { W = wq; bias = bq; out = (float*)g_q; N = 2048; n0 = bx * 128; }
    else if (bx < 20) { W = wk; bias = bk; out = out_k; N = 512; n0 = (bx - 16) * 128; }
    else              { W = wv; bias = bv; out = out_v; N = 512; n0 = (bx - 20) * 128; }
    gemm_body(x, W, bias, out, N, 1, blockIdx.y * 128, n0);
}

__global__ __launch_bounds__(128, 2) void oproj_gemm(
    const float* __restrict__ wo, float* __restrict__ out)
{
    gemm_body((const float*)g_attn, wo, nullptr, out, 2048, 0,
              blockIdx.y * 128, blockIdx.x * 128);
}

// ---------------------------------------------------------------------------
// RoPE in place, fused q (g_q) + k (out_k): pair (j, j+64)
// ---------------------------------------------------------------------------
#define PQ (B_ * H_ * T_ * 64)
#define PK (B_ * KV_ * T_ * 64)

__global__ void rope_all(float* __restrict__ out_k)
{
    int idx = blockIdx.x * blockDim.x + threadIdx.x;
    float* x;
    if (idx < PQ) { x = (float*)g_q; }
    else          { x = out_k; idx -= PQ; if (idx >= PK) return; }

    const int j = idx & 63;
    const int t = (idx >> 6) & (T_ - 1);
    const int bh = idx >> 17;

    const float freq = expf(-13.815510557964274f * ((float)j / 64.0f));
    const float theta = (float)t * freq;
    const float s = sinf(theta);
    const float c = cosf(theta);

    float* base = x + ((size_t)bh * T_ + t) * D_;
    const float v1 = base[j];
    const float v2 = base[j + 64];
    base[j]      = c * v1 - s * v2;
    base[j + 64] = c * v2 + s * v1;
}

// ---------------------------------------------------------------------------
// Flash attention with tf32 MMA — exact r9 version (proven 1208 us config).
// ---------------------------------------------------------------------------
#define QF_OFF 0
#define KF_OFF 16384
#define VF_OFF 24576
#define PF_OFF 32768
#define FL_SMEM_WORDS 40960   // 160 KB

__global__ __launch_bounds__(256, 1) void flash_mma(
    const float* __restrict__ k, const float* __restrict__ v)
{
    extern __shared__ uint32_t sm[];
    uint32_t* Qf = sm + QF_OFF;
    uint32_t* Kf = sm + KF_OFF;
    uint32_t* Vf = sm + VF_OFF;
    uint32_t* Pf = sm + PF_OFF;

    const int tid = threadIdx.x;
    const int lane = tid & 31;
    const int wid = tid >> 5;
    const int g = lane >> 2;
    const int t = lane & 3;

    const int q0 = (int)(gridDim.x - 1 - blockIdx.x) * 128;
    const int h  = blockIdx.y;
    const int b  = blockIdx.z;
    const int kvh = h >> 2;

    const float* qp = (const float*)g_q + ((size_t)(b * H_ + h) * T_ + q0) * D_;
    const float* kp = k + ((size_t)(b * KV_ + kvh) * T_) * D_;
    const float* vp = v + ((size_t)(b * KV_ + kvh) * T_) * D_;

    {
        const int mrow  = tid >> 1;
        const int dbase = (tid & 1) * 64;
        const int stripe = mrow >> 4;
        const int r  = mrow & 15;
        const int gg = r & 7;
        const int i0 = r >> 3;
        const float* qrow = qp + (size_t)mrow * D_;
#pragma unroll
        for (int it = 0; it < 16; it++) {
            const int d0 = dbase + it * 4;
            float4 q4 = *(const float4*)(qrow + d0);
            float vals[4] = {q4.x, q4.y, q4.z, q4.w};
#pragma unroll
            for (int j = 0; j < 4; j++) {
                const int dd = d0 + j;
                const int c = dd >> 3, u = dd & 7;
                Qf[(((stripe * 16 + c) * 32) + gg * 4 + (u & 3)) * 4 +
                   (i0 | ((u >> 2) << 1))] = f2tf32(vals[j]);
            }
        }
    }

    float acc_o[16][4];
#pragma unroll
    for (int nt = 0; nt < 16; nt++)
#pragma unroll
        for (int i = 0; i < 4; i++) acc_o[nt][i] = 0.0f;

    float m0 = -INFINITY, m1 = -INFINITY, l0 = 0.0f, l1 = 0.0f;
    const float scale = 0.08838834764831845f;

    const int r0 = q0 + wid * 16 + g;
    const int r1 = r0 + 8;
    const int warp_last = q0 + wid * 16 + 15;
    const int ntiles = q0 / 64 + 2;

    const int srow = tid >> 2;
    const int dbv  = (tid & 3) * 32;
    const int ntk = srow >> 3;
    const int gk  = srow & 7;
    const int csV = srow >> 3;
    const int usV = srow & 7;
    const int tsV = usV & 3;
    const int hsV = usV >> 2;

    for (int ti = 0; ti < ntiles; ti++) {
        const int s0 = ti * 64;
        __syncthreads();
        {
            const float* krow = kp + (size_t)(s0 + srow) * D_;
            const float* vrow = vp + (size_t)(s0 + srow) * D_;
#pragma unroll
            for (int it = 0; it < 8; it++) {
                const int d0 = dbv + it * 4;
                float4 k4 = *(const float4*)(krow + d0);
                float4 v4 = *(const float4*)(vrow + d0);
                float kv[4] = {k4.x, k4.y, k4.z, k4.w};
                float vv[4] = {v4.x, v4.y, v4.z, v4.w};
#pragma unroll
                for (int j = 0; j < 4; j++) {
                    const int dd = d0 + j;
                    const int ck = dd >> 3, uk = dd & 7;
                    Kf[((ntk * 16 + ck) * 32 + gk * 4 + (uk & 3)) * 2 + (uk >> 2)] =
                        f2tf32(kv[j]);
                    const int ntv = dd >> 3, gv = dd & 7;
                    Vf[((ntv * 8 + csV) * 32 + gv * 4 + tsV) * 2 + hsV] =
                        f2tf32(vv[j]);
                }
            }
        }
        __syncthreads();

        if (s0 > warp_last) continue;

        float accs[8][4];
#pragma unroll
        for (int nt = 0; nt < 8; nt++)
#pragma unroll
            for (int i = 0; i < 4; i++) accs[nt][i] = 0.0f;

#pragma unroll
        for (int c = 0; c < 16; c++) {
            uint4 a = *(const uint4*)&Qf[((wid * 16 + c) * 32 + lane) * 4];
#pragma unroll
            for (int nt = 0; nt < 8; nt++) {
                uint2 bb = *(const uint2*)&Kf[((nt * 16 + c) * 32 + lane) * 2];
                mma_tf32(accs[nt], a.x, a.y, a.z, a.w, bb.x, bb.y);
            }
        }

        float mx0 = -INFINITY, mx1 = -INFINITY;
#pragma unroll
        for (int nt = 0; nt < 8; nt++) {
            const int c0 = s0 + nt * 8 + 2 * t;
            accs[nt][0] = (c0     <= r0) ? accs[nt][0] * scale : -INFINITY;
            accs[nt][1] = (c0 + 1 <= r0) ? accs[nt][1] * scale : -INFINITY;
            accs[nt][2] = (c0     <= r1) ? accs[nt][2] * scale : -INFINITY;
            accs[nt][3] = (c0 + 1 <= r1) ? accs[nt][3] * scale : -INFINITY;
            mx0 = fmaxf(mx0, fmaxf(accs[nt][0], accs[nt][1]));
            mx1 = fmaxf(mx1, fmaxf(accs[nt][2], accs[nt][3]));
        }
        mx0 = fmaxf(mx0, __shfl_xor_sync(0xffffffffu, mx0, 1));
        mx0 = fmaxf(mx0, __shfl_xor_sync(0xffffffffu, mx0, 2));
        mx1 = fmaxf(mx1, __shfl_xor_sync(0xffffffffu, mx1, 1));
        mx1 = fmaxf(mx1, __shfl_xor_sync(0xffffffffu, mx1, 2));

        const float mn0 = fmaxf(m0, mx0);
        const float mn1 = fmaxf(m1, mx1);
        const float corr0 = __expf(m0 - mn0);
        const float corr1 = __expf(m1 - mn1);
        m0 = mn0; m1 = mn1;

        float s0s = 0.0f, s1s = 0.0f;
#pragma unroll
        for (int nt = 0; nt < 8; nt++) {
            accs[nt][0] = __expf(accs[nt][0] - mn0);
            accs[nt][1] = __expf(accs[nt][1] - mn0);
            accs[nt][2] = __expf(accs[nt][2] - mn1);
            accs[nt][3] = __expf(accs[nt][3] - mn1);
            s0s += accs[nt][0] + accs[nt][1];
            s1s += accs[nt][2] + accs[nt][3];
        }
        s0s += __shfl_xor_sync(0xffffffffu, s0s, 1);
        s0s += __shfl_xor_sync(0xffffffffu, s0s, 2);
        s1s += __shfl_xor_sync(0xffffffffu, s1s, 1);
        s1s += __shfl_xor_sync(0xffffffffu, s1s, 2);
        l0 = l0 * corr0 + s0s;
        l1 = l1 * corr1 + s1s;

#pragma unroll
        for (int nt = 0; nt < 16; nt++) {
            acc_o[nt][0] *= corr0; acc_o[nt][1] *= corr0;
            acc_o[nt][2] *= corr1; acc_o[nt][3] *= corr1;
        }

        __syncwarp();
#pragma unroll
        for (int nt = 0; nt < 8; nt++) {
            const int u0 = 2 * t, u1 = 2 * t + 1;
            const int base = (wid * 8 + nt) * 32 + g * 4;
            Pf[(base + (u0 & 3)) * 4 + ((u0 >> 2) << 1) + 0] = f2tf32(accs[nt][0]);
            Pf[(base + (u0 & 3)) * 4 + ((u0 >> 2) << 1) + 1] = f2tf32(accs[nt][2]);
            Pf[(base + (u1 & 3)) * 4 + ((u1 >> 2) << 1) + 0] = f2tf32(accs[nt][1]);
            Pf[(base + (u1 & 3)) * 4 + ((u1 >> 2) << 1) + 1] = f2tf32(accs[nt][3]);
        }
        __syncwarp();

#pragma unroll
        for (int c = 0; c < 8; c++) {
            uint4 a = *(const uint4*)&Pf[((wid * 8 + c) * 32 + lane) * 4];
#pragma unroll
            for (int nt = 0; nt < 16; nt++) {
                uint2 bb = *(const uint2*)&Vf[((nt * 8 + c) * 32 + lane) * 2];
                mma_tf32(acc_o[nt], a.x, a.y, a.z, a.w, bb.x, bb.y);
            }
        }
    }

    const float inv0 = 1.0f / l0;
    const float inv1 = 1.0f / l1;
    float* o = (float*)g_attn;
    const size_t ro0 = ((size_t)(b * T_ + r0)) * C_ + h * D_;
    const size_t ro1 = ((size_t)(b * T_ + r1)) * C_ + h * D_;
#pragma unroll
    for (int nt = 0; nt < 16; nt++) {
        const int col = nt * 8 + 2 * t;
        float2 w0, w1;
        w0.x = acc_o[nt][0] * inv0; w0.y = acc_o[nt][1] * inv0;
        w1.x = acc_o[nt][2] * inv1; w1.y = acc_o[nt][3] * inv1;
        *(float2*)&o[ro0 + col] = w0;
        *(float2*)&o[ro1 + col] = w1;
    }
}

// ---------------------------------------------------------------------------
extern "C" void kernel_launch(void* const* d_in, const int* in_sizes, int n_in,
                              void* d_out, int out_size)
{
    const float* x  = (const float*)d_in[0];
    const float* wq = (const float*)d_in[1];
    const float* bq = (const float*)d_in[2];
    const float* wk = (const float*)d_in[3];
    const float* bk = (const float*)d_in[4];
    const float* wv = (const float*)d_in[5];
    const float* bv = (const float*)d_in[6];
    const float* wo = (const float*)d_in[7];

    float* out_main = (float*)d_out;                    // [B,T,C]
    float* out_k = out_main + (size_t)B_ * T_ * C_;     // [B,KV,T,D]
    float* out_v = out_k + (size_t)B_ * KV_ * T_ * D_;  // [B,KV,T,D]

    const int M = B_ * T_;  // 4096

    // Fused QKV projection
    {
        dim3 g(24, M / 128);
        qkv_gemm<<<g, 128>>>(x, wq, bq, wk, bk, wv, bv, out_k, out_v);
    }

    // RoPE on q (g_q) and k (out_k), fused single launch
    {
        const int total = PQ + PK;
        rope_all<<<(total + 255) / 256, 256>>>(out_k);
    }

    // Flash attention (tf32 MMA, r9 config)
    {
        const int smem = FL_SMEM_WORDS * (int)sizeof(uint32_t);  // 163840
        cudaFuncSetAttribute(flash_mma,
                             cudaFuncAttributeMaxDynamicSharedMemorySize, smem);
        dim3 g(T_ / 128, H_, B_);
        flash_mma<<<g, 256, smem>>>(out_k, out_v);
    }

    // Output projection
    {
        dim3 go(C_ / 128, M / 128);
        oproj_gemm<<<go, 128>>>(wo, out_main);
    }
}

// round 12
// speedup vs baseline: 1.5924x; 1.4710x over previous
#include <cuda_runtime.h>
#include <math.h>
#include <stdint.h>

#define B_  2
#define T_  2048
#define C_  2048
#define H_  16
#define KV_ 4
#define D_  128
#define REP_ 4
#define KDIM 2048

// Scratch (allocation-free rule: __device__ globals)
__device__ float g_q[B_ * H_ * T_ * D_];     // [B,H,T,D] q (pre/post rope)
__device__ float g_attn[B_ * T_ * H_ * D_];  // [B,T,H*D] attention output rows

// ---------------------------------------------------------------------------
// tf32 helpers
// ---------------------------------------------------------------------------
__device__ __forceinline__ uint32_t f2tf32(float f) {
    uint32_t u;
    asm("cvt.rna.tf32.f32 %0, %1;" : "=r"(u) : "f"(f));
    return u;
}

__device__ __forceinline__ void mma_tf32(float c[4],
                                         uint32_t a0, uint32_t a1, uint32_t a2, uint32_t a3,
                                         uint32_t b0, uint32_t b1) {
    asm volatile(
        "mma.sync.aligned.m16n8k8.row.col.f32.tf32.tf32.f32 "
        "{%0,%1,%2,%3}, {%4,%5,%6,%7}, {%8,%9}, {%0,%1,%2,%3};"
        : "+f"(c[0]), "+f"(c[1]), "+f"(c[2]), "+f"(c[3])
        : "r"(a0), "r"(a1), "r"(a2), "r"(a3), "r"(b0), "r"(b1));
}

// ---------------------------------------------------------------------------
// tf32 GEMM, 64x64 warp tiles (r9-proven): out = A[M,2048] @ W[2048,N] (+bias)
// CTA tile 128x128, 128 threads, BK=16, register-prefetch mainloop.
// mode 0: row-major out[M,N]; mode 1: scatter [B, N/128 heads, T, 128].
// ---------------------------------------------------------------------------
#define SA 20
#define SB 136

__device__ __forceinline__ void gemm_body(
    const float* __restrict__ A, const float* __restrict__ W,
    const float* __restrict__ bias, float* __restrict__ out,
    int N, int mode, int m0, int n0)
{
    __shared__ uint32_t As[128 * SA];
    __shared__ uint32_t Bs[16 * SB];

    const int tid  = threadIdx.x;          // 0..127
    const int wid  = tid >> 5;             // 0..3
    const int lane = tid & 31;
    const int g = lane >> 2;
    const int t = lane & 3;
    const int warp_m = (wid & 1) * 64;
    const int warp_n = (wid >> 1) * 64;

    float acc[4][8][4];
#pragma unroll
    for (int mt = 0; mt < 4; mt++)
#pragma unroll
        for (int nt = 0; nt < 8; nt++)
#pragma unroll
            for (int i = 0; i < 4; i++) acc[mt][nt][i] = 0.0f;

    const int aRow = tid >> 2;             // 0..31
    const int aCol = (tid & 3) * 4;
    const int bRow = tid >> 5;             // 0..3
    const int bCol = (tid & 31) * 4;

    const float* pa = A + (size_t)(m0 + aRow) * KDIM + aCol;
    const float* pb = W + (size_t)bRow * N + n0 + bCol;

    float4 av[4], bv[4];
#pragma unroll
    for (int c = 0; c < 4; c++) {
        av[c] = *(const float4*)(pa + (size_t)(32 * c) * KDIM);
        bv[c] = *(const float4*)(pb + (size_t)(4 * c) * N);
    }

    for (int k0 = 0; k0 < KDIM; k0 += 16) {
        __syncthreads();
#pragma unroll
        for (int c = 0; c < 4; c++) {
            uint32_t* qa = &As[(aRow + 32 * c) * SA + aCol];
            qa[0] = f2tf32(av[c].x); qa[1] = f2tf32(av[c].y);
            qa[2] = f2tf32(av[c].z); qa[3] = f2tf32(av[c].w);
            uint32_t* qb = &Bs[(bRow + 4 * c) * SB + bCol];
            qb[0] = f2tf32(bv[c].x); qb[1] = f2tf32(bv[c].y);
            qb[2] = f2tf32(bv[c].z); qb[3] = f2tf32(bv[c].w);
        }
        __syncthreads();

        if (k0 + 16 < KDIM) {
            pa += 16;
            pb += (size_t)16 * N;
#pragma unroll
            for (int c = 0; c < 4; c++) {
                av[c] = *(const float4*)(pa + (size_t)(32 * c) * KDIM);
                bv[c] = *(const float4*)(pb + (size_t)(4 * c) * N);
            }
        }

#pragma unroll
        for (int kk = 0; kk < 16; kk += 8) {
            uint32_t afr[4][4];
#pragma unroll
            for (int mt = 0; mt < 4; mt++) {
                const int rb = warp_m + mt * 16;
                afr[mt][0] = As[(rb + g)     * SA + kk + t];
                afr[mt][1] = As[(rb + g + 8) * SA + kk + t];
                afr[mt][2] = As[(rb + g)     * SA + kk + t + 4];
                afr[mt][3] = As[(rb + g + 8) * SA + kk + t + 4];
            }
            uint32_t bfr[8][2];
#pragma unroll
            for (int nt = 0; nt < 8; nt++) {
                const int cn = warp_n + nt * 8 + g;
                bfr[nt][0] = Bs[(kk + t)     * SB + cn];
                bfr[nt][1] = Bs[(kk + t + 4) * SB + cn];
            }
#pragma unroll
            for (int mt = 0; mt < 4; mt++)
#pragma unroll
                for (int nt = 0; nt < 8; nt++)
                    mma_tf32(acc[mt][nt],
                             afr[mt][0], afr[mt][1], afr[mt][2], afr[mt][3],
                             bfr[nt][0], bfr[nt][1]);
        }
    }

#pragma unroll
    for (int mt = 0; mt < 4; mt++) {
#pragma unroll
        for (int nt = 0; nt < 8; nt++) {
            const int col = n0 + warp_n + nt * 8 + 2 * t;
            float bx = 0.0f, by = 0.0f;
            if (bias) { bx = bias[col]; by = bias[col + 1]; }
#pragma unroll
            for (int half = 0; half < 2; half++) {
                const int m = m0 + warp_m + mt * 16 + g + half * 8;
                float2 r;
                r.x = acc[mt][nt][half * 2 + 0] + bx;
                r.y = acc[mt][nt][half * 2 + 1] + by;
                if (mode == 0) {
                    *(float2*)&out[(size_t)m * N + col] = r;
                } else {
                    const int b  = m >> 11;
                    const int tt = m & (T_ - 1);
                    const int h  = col >> 7;
                    const int dd = col & 127;
                    *(float2*)&out[((size_t)(b * (N >> 7) + h) * T_ + tt) * D_ + dd] = r;
                }
            }
        }
    }
}

// Fused QKV: grid.x = 24 (0..15 Q tiles, 16..19 K tiles, 20..23 V tiles)
__global__ __launch_bounds__(128, 2) void qkv_gemm(
    const float* __restrict__ x,
    const float* __restrict__ wq, const float* __restrict__ bq,
    const float* __restrict__ wk, const float* __restrict__ bk,
    const float* __restrict__ wv, const float* __restrict__ bv,
    float* __restrict__ out_k, float* __restrict__ out_v)
{
    const int bx = blockIdx.x;
    const float* W; const float* bias; float* out; int N; int n0;
    if (bx < 16)      { W = wq; bias = bq; out = (float*)g_q; N = 2048; n0 = bx * 128; }
    else if (bx < 20) { W = wk; bias = bk; out = out_k; N = 512; n0 = (bx - 16) * 128; }
    else              { W = wv; bias = bv; out = out_v; N = 512; n0 = (bx - 20) * 128; }
    gemm_body(x, W, bias, out, N, 1, blockIdx.y * 128, n0);
}

__global__ __launch_bounds__(128, 2) void oproj_gemm(
    const float* __restrict__ wo, float* __restrict__ out)
{
    gemm_body((const float*)g_attn, wo, nullptr, out, 2048, 0,
              blockIdx.y * 128, blockIdx.x * 128);
}

// ---------------------------------------------------------------------------
// RoPE in place, fused q (g_q) + k (out_k): pair (j, j+64)
// ---------------------------------------------------------------------------
#define PQ (B_ * H_ * T_ * 64)
#define PK (B_ * KV_ * T_ * 64)

__global__ void rope_all(float* __restrict__ out_k)
{
    int idx = blockIdx.x * blockDim.x + threadIdx.x;
    float* x;
    if (idx < PQ) { x = (float*)g_q; }
    else          { x = out_k; idx -= PQ; if (idx >= PK) return; }

    const int j = idx & 63;
    const int t = (idx >> 6) & (T_ - 1);
    const int bh = idx >> 17;

    const float freq = expf(-13.815510557964274f * ((float)j / 64.0f));
    const float theta = (float)t * freq;
    const float s = sinf(theta);
    const float c = cosf(theta);

    float* base = x + ((size_t)bh * T_ + t) * D_;
    const float v1 = base[j];
    const float v2 = base[j + 64];
    base[j]      = c * v1 - s * v2;
    base[j + 64] = c * v2 + s * v1;
}

// ---------------------------------------------------------------------------
// Flash attention with tf32 MMA — exact r9 version (best-known config).
// ---------------------------------------------------------------------------
#define QF_OFF 0
#define KF_OFF 16384
#define VF_OFF 24576
#define PF_OFF 32768
#define FL_SMEM_WORDS 40960   // 160 KB

__global__ __launch_bounds__(256, 1) void flash_mma(
    const float* __restrict__ k, const float* __restrict__ v)
{
    extern __shared__ uint32_t sm[];
    uint32_t* Qf = sm + QF_OFF;
    uint32_t* Kf = sm + KF_OFF;
    uint32_t* Vf = sm + VF_OFF;
    uint32_t* Pf = sm + PF_OFF;

    const int tid = threadIdx.x;
    const int lane = tid & 31;
    const int wid = tid >> 5;
    const int g = lane >> 2;
    const int t = lane & 3;

    const int q0 = (int)(gridDim.x - 1 - blockIdx.x) * 128;
    const int h  = blockIdx.y;
    const int b  = blockIdx.z;
    const int kvh = h >> 2;

    const float* qp = (const float*)g_q + ((size_t)(b * H_ + h) * T_ + q0) * D_;
    const float* kp = k + ((size_t)(b * KV_ + kvh) * T_) * D_;
    const float* vp = v + ((size_t)(b * KV_ + kvh) * T_) * D_;

    {
        const int mrow  = tid >> 1;
        const int dbase = (tid & 1) * 64;
        const int stripe = mrow >> 4;
        const int r  = mrow & 15;
        const int gg = r & 7;
        const int i0 = r >> 3;
        const float* qrow = qp + (size_t)mrow * D_;
#pragma unroll
        for (int it = 0; it < 16; it++) {
            const int d0 = dbase + it * 4;
            float4 q4 = *(const float4*)(qrow + d0);
            float vals[4] = {q4.x, q4.y, q4.z, q4.w};
#pragma unroll
            for (int j = 0; j < 4; j++) {
                const int dd = d0 + j;
                const int c = dd >> 3, u = dd & 7;
                Qf[(((stripe * 16 + c) * 32) + gg * 4 + (u & 3)) * 4 +
                   (i0 | ((u >> 2) << 1))] = f2tf32(vals[j]);
            }
        }
    }

    float acc_o[16][4];
#pragma unroll
    for (int nt = 0; nt < 16; nt++)
#pragma unroll
        for (int i = 0; i < 4; i++) acc_o[nt][i] = 0.0f;

    float m0 = -INFINITY, m1 = -INFINITY, l0 = 0.0f, l1 = 0.0f;
    const float scale = 0.08838834764831845f;

    const int r0 = q0 + wid * 16 + g;
    const int r1 = r0 + 8;
    const int warp_last = q0 + wid * 16 + 15;
    const int ntiles = q0 / 64 + 2;

    const int srow = tid >> 2;
    const int dbv  = (tid & 3) * 32;
    const int ntk = srow >> 3;
    const int gk  = srow & 7;
    const int csV = srow >> 3;
    const int usV = srow & 7;
    const int tsV = usV & 3;
    const int hsV = usV >> 2;

    for (int ti = 0; ti < ntiles; ti++) {
        const int s0 = ti * 64;
        __syncthreads();
        {
            const float* krow = kp + (size_t)(s0 + srow) * D_;
            const float* vrow = vp + (size_t)(s0 + srow) * D_;
#pragma unroll
            for (int it = 0; it < 8; it++) {
                const int d0 = dbv + it * 4;
                float4 k4 = *(const float4*)(krow + d0);
                float4 v4 = *(const float4*)(vrow + d0);
                float kv[4] = {k4.x, k4.y, k4.z, k4.w};
                float vv[4] = {v4.x, v4.y, v4.z, v4.w};
#pragma unroll
                for (int j = 0; j < 4; j++) {
                    const int dd = d0 + j;
                    const int ck = dd >> 3, uk = dd & 7;
                    Kf[((ntk * 16 + ck) * 32 + gk * 4 + (uk & 3)) * 2 + (uk >> 2)] =
                        f2tf32(kv[j]);
                    const int ntv = dd >> 3, gv = dd & 7;
                    Vf[((ntv * 8 + csV) * 32 + gv * 4 + tsV) * 2 + hsV] =
                        f2tf32(vv[j]);
                }
            }
        }
        __syncthreads();

        if (s0 > warp_last) continue;

        float accs[8][4];
#pragma unroll
        for (int nt = 0; nt < 8; nt++)
#pragma unroll
            for (int i = 0; i < 4; i++) accs[nt][i] = 0.0f;

#pragma unroll
        for (int c = 0; c < 16; c++) {
            uint4 a = *(const uint4*)&Qf[((wid * 16 + c) * 32 + lane) * 4];
#pragma unroll
            for (int nt = 0; nt < 8; nt++) {
                uint2 bb = *(const uint2*)&Kf[((nt * 16 + c) * 32 + lane) * 2];
                mma_tf32(accs[nt], a.x, a.y, a.z, a.w, bb.x, bb.y);
            }
        }

        float mx0 = -INFINITY, mx1 = -INFINITY;
#pragma unroll
        for (int nt = 0; nt < 8; nt++) {
            const int c0 = s0 + nt * 8 + 2 * t;
            accs[nt][0] = (c0     <= r0) ? accs[nt][0] * scale : -INFINITY;
            accs[nt][1] = (c0 + 1 <= r0) ? accs[nt][1] * scale : -INFINITY;
            accs[nt][2] = (c0     <= r1) ? accs[nt][2] * scale : -INFINITY;
            accs[nt][3] = (c0 + 1 <= r1) ? accs[nt][3] * scale : -INFINITY;
            mx0 = fmaxf(mx0, fmaxf(accs[nt][0], accs[nt][1]));
            mx1 = fmaxf(mx1, fmaxf(accs[nt][2], accs[nt][3]));
        }
        mx0 = fmaxf(mx0, __shfl_xor_sync(0xffffffffu, mx0, 1));
        mx0 = fmaxf(mx0, __shfl_xor_sync(0xffffffffu, mx0, 2));
        mx1 = fmaxf(mx1, __shfl_xor_sync(0xffffffffu, mx1, 1));
        mx1 = fmaxf(mx1, __shfl_xor_sync(0xffffffffu, mx1, 2));

        const float mn0 = fmaxf(m0, mx0);
        const float mn1 = fmaxf(m1, mx1);
        const float corr0 = __expf(m0 - mn0);
        const float corr1 = __expf(m1 - mn1);
        m0 = mn0; m1 = mn1;

        float s0s = 0.0f, s1s = 0.0f;
#pragma unroll
        for (int nt = 0; nt < 8; nt++) {
            accs[nt][0] = __expf(accs[nt][0] - mn0);
            accs[nt][1] = __expf(accs[nt][1] - mn0);
            accs[nt][2] = __expf(accs[nt][2] - mn1);
            accs[nt][3] = __expf(accs[nt][3] - mn1);
            s0s += accs[nt][0] + accs[nt][1];
            s1s += accs[nt][2] + accs[nt][3];
        }
        s0s += __shfl_xor_sync(0xffffffffu, s0s, 1);
        s0s += __shfl_xor_sync(0xffffffffu, s0s, 2);
        s1s += __shfl_xor_sync(0xffffffffu, s1s, 1);
        s1s += __shfl_xor_sync(0xffffffffu, s1s, 2);
        l0 = l0 * corr0 + s0s;
        l1 = l1 * corr1 + s1s;

#pragma unroll
        for (int nt = 0; nt < 16; nt++) {
            acc_o[nt][0] *= corr0; acc_o[nt][1] *= corr0;
            acc_o[nt][2] *= corr1; acc_o[nt][3] *= corr1;
        }

        __syncwarp();
#pragma unroll
        for (int nt = 0; nt < 8; nt++) {
            const int u0 = 2 * t, u1 = 2 * t + 1;
            const int base = (wid * 8 + nt) * 32 + g * 4;
            Pf[(base + (u0 & 3)) * 4 + ((u0 >> 2) << 1) + 0] = f2tf32(accs[nt][0]);
            Pf[(base + (u0 & 3)) * 4 + ((u0 >> 2) << 1) + 1] = f2tf32(accs[nt][2]);
            Pf[(base + (u1 & 3)) * 4 + ((u1 >> 2) << 1) + 0] = f2tf32(accs[nt][1]);
            Pf[(base + (u1 & 3)) * 4 + ((u1 >> 2) << 1) + 1] = f2tf32(accs[nt][3]);
        }
        __syncwarp();

#pragma unroll
        for (int c = 0; c < 8; c++) {
            uint4 a = *(const uint4*)&Pf[((wid * 8 + c) * 32 + lane) * 4];
#pragma unroll
            for (int nt = 0; nt < 16; nt++) {
                uint2 bb = *(const uint2*)&Vf[((nt * 8 + c) * 32 + lane) * 2];
                mma_tf32(acc_o[nt], a.x, a.y, a.z, a.w, bb.x, bb.y);
            }
        }
    }

    const float inv0 = 1.0f / l0;
    const float inv1 = 1.0f / l1;
    float* o = (float*)g_attn;
    const size_t ro0 = ((size_t)(b * T_ + r0)) * C_ + h * D_;
    const size_t ro1 = ((size_t)(b * T_ + r1)) * C_ + h * D_;
#pragma unroll
    for (int nt = 0; nt < 16; nt++) {
        const int col = nt * 8 + 2 * t;
        float2 w0, w1;
        w0.x = acc_o[nt][0] * inv0; w0.y = acc_o[nt][1] * inv0;
        w1.x = acc_o[nt][2] * inv1; w1.y = acc_o[nt][3] * inv1;
        *(float2*)&o[ro0 + col] = w0;
        *(float2*)&o[ro1 + col] = w1;
    }
}

// ---------------------------------------------------------------------------
extern "C" void kernel_launch(void* const* d_in, const int* in_sizes, int n_in,
                              void* d_out, int out_size)
{
    const float* x  = (const float*)d_in[0];
    const float* wq = (const float*)d_in[1];
    const float* bq = (const float*)d_in[2];
    const float* wk = (const float*)d_in[3];
    const float* bk = (const float*)d_in[4];
    const float* wv = (const float*)d_in[5];
    const float* bv = (const float*)d_in[6];
    const float* wo = (const float*)d_in[7];

    float* out_main = (float*)d_out;                    // [B,T,C]
    float* out_k = out_main + (size_t)B_ * T_ * C_;     // [B,KV,T,D]
    float* out_v = out_k + (size_t)B_ * KV_ * T_ * D_;  // [B,KV,T,D]

    const int M = B_ * T_;  // 4096

    // Fused QKV projection
    {
        dim3 g(24, M / 128);
        qkv_gemm<<<g, 128>>>(x, wq, bq, wk, bk, wv, bv, out_k, out_v);
    }

    // RoPE on q (g_q) and k (out_k), fused single launch
    {
        const int total = PQ + PK;
        rope_all<<<(total + 255) / 256, 256>>>(out_k);
    }

    // Flash attention (tf32 MMA, r9 config)
    {
        const int smem = FL_SMEM_WORDS * (int)sizeof(uint32_t);  // 163840
        cudaFuncSetAttribute(flash_mma,
                             cudaFuncAttributeMaxDynamicSharedMemorySize, smem);
        dim3 g(T_ / 128, H_, B_);
        flash_mma<<<g, 256, smem>>>(out_k, out_v);
    }

    // Output projection
    {
        dim3 go(C_ / 128, M / 128);
        oproj_gemm<<<go, 128>>>(wo, out_main);
    }
}

// round 13
// speedup vs baseline: 1.6599x; 1.0424x over previous
#include <cuda_runtime.h>
#include <math.h>
#include <stdint.h>

#define B_  2
#define T_  2048
#define C_  2048
#define H_  16
#define KV_ 4
#define D_  128
#define REP_ 4
#define KDIM 2048

// Scratch (allocation-free rule: __device__ globals)
__device__ float g_q[B_ * H_ * T_ * D_];     // [B,H,T,D] q (pre/post rope)
__device__ float g_attn[B_ * T_ * H_ * D_];  // [B,T,H*D] attention output rows

// ---------------------------------------------------------------------------
// tf32 helpers
// ---------------------------------------------------------------------------
__device__ __forceinline__ uint32_t f2tf32(float f) {
    uint32_t u;
    asm("cvt.rna.tf32.f32 %0, %1;" : "=r"(u) : "f"(f));
    return u;
}

__device__ __forceinline__ void mma_tf32(float c[4],
                                         uint32_t a0, uint32_t a1, uint32_t a2, uint32_t a3,
                                         uint32_t b0, uint32_t b1) {
    asm volatile(
        "mma.sync.aligned.m16n8k8.row.col.f32.tf32.tf32.f32 "
        "{%0,%1,%2,%3}, {%4,%5,%6,%7}, {%8,%9}, {%0,%1,%2,%3};"
        : "+f"(c[0]), "+f"(c[1]), "+f"(c[2]), "+f"(c[3])
        : "r"(a0), "r"(a1), "r"(a2), "r"(a3), "r"(b0), "r"(b1));
}

// ---------------------------------------------------------------------------
// tf32 GEMM, 64x64 warp tiles (r9-proven): out = A[M,2048] @ W[2048,N] (+bias)
// ---------------------------------------------------------------------------
#define SA 20
#define SB 136

__device__ __forceinline__ void gemm_body(
    const float* __restrict__ A, const float* __restrict__ W,
    const float* __restrict__ bias, float* __restrict__ out,
    int N, int mode, int m0, int n0)
{
    __shared__ uint32_t As[128 * SA];
    __shared__ uint32_t Bs[16 * SB];

    const int tid  = threadIdx.x;          // 0..127
    const int wid  = tid >> 5;             // 0..3
    const int lane = tid & 31;
    const int g = lane >> 2;
    const int t = lane & 3;
    const int warp_m = (wid & 1) * 64;
    const int warp_n = (wid >> 1) * 64;

    float acc[4][8][4];
#pragma unroll
    for (int mt = 0; mt < 4; mt++)
#pragma unroll
        for (int nt = 0; nt < 8; nt++)
#pragma unroll
            for (int i = 0; i < 4; i++) acc[mt][nt][i] = 0.0f;

    const int aRow = tid >> 2;
    const int aCol = (tid & 3) * 4;
    const int bRow = tid >> 5;
    const int bCol = (tid & 31) * 4;

    const float* pa = A + (size_t)(m0 + aRow) * KDIM + aCol;
    const float* pb = W + (size_t)bRow * N + n0 + bCol;

    float4 av[4], bv[4];
#pragma unroll
    for (int c = 0; c < 4; c++) {
        av[c] = *(const float4*)(pa + (size_t)(32 * c) * KDIM);
        bv[c] = *(const float4*)(pb + (size_t)(4 * c) * N);
    }

    for (int k0 = 0; k0 < KDIM; k0 += 16) {
        __syncthreads();
#pragma unroll
        for (int c = 0; c < 4; c++) {
            uint32_t* qa = &As[(aRow + 32 * c) * SA + aCol];
            qa[0] = f2tf32(av[c].x); qa[1] = f2tf32(av[c].y);
            qa[2] = f2tf32(av[c].z); qa[3] = f2tf32(av[c].w);
            uint32_t* qb = &Bs[(bRow + 4 * c) * SB + bCol];
            qb[0] = f2tf32(bv[c].x); qb[1] = f2tf32(bv[c].y);
            qb[2] = f2tf32(bv[c].z); qb[3] = f2tf32(bv[c].w);
        }
        __syncthreads();

        if (k0 + 16 < KDIM) {
            pa += 16;
            pb += (size_t)16 * N;
#pragma unroll
            for (int c = 0; c < 4; c++) {
                av[c] = *(const float4*)(pa + (size_t)(32 * c) * KDIM);
                bv[c] = *(const float4*)(pb + (size_t)(4 * c) * N);
            }
        }

#pragma unroll
        for (int kk = 0; kk < 16; kk += 8) {
            uint32_t afr[4][4];
#pragma unroll
            for (int mt = 0; mt < 4; mt++) {
                const int rb = warp_m + mt * 16;
                afr[mt][0] = As[(rb + g)     * SA + kk + t];
                afr[mt][1] = As[(rb + g + 8) * SA + kk + t];
                afr[mt][2] = As[(rb + g)     * SA + kk + t + 4];
                afr[mt][3] = As[(rb + g + 8) * SA + kk + t + 4];
            }
            uint32_t bfr[8][2];
#pragma unroll
            for (int nt = 0; nt < 8; nt++) {
                const int cn = warp_n + nt * 8 + g;
                bfr[nt][0] = Bs[(kk + t)     * SB + cn];
                bfr[nt][1] = Bs[(kk + t + 4) * SB + cn];
            }
#pragma unroll
            for (int mt = 0; mt < 4; mt++)
#pragma unroll
                for (int nt = 0; nt < 8; nt++)
                    mma_tf32(acc[mt][nt],
                             afr[mt][0], afr[mt][1], afr[mt][2], afr[mt][3],
                             bfr[nt][0], bfr[nt][1]);
        }
    }

#pragma unroll
    for (int mt = 0; mt < 4; mt++) {
#pragma unroll
        for (int nt = 0; nt < 8; nt++) {
            const int col = n0 + warp_n + nt * 8 + 2 * t;
            float bx = 0.0f, by = 0.0f;
            if (bias) { bx = bias[col]; by = bias[col + 1]; }
#pragma unroll
            for (int half = 0; half < 2; half++) {
                const int m = m0 + warp_m + mt * 16 + g + half * 8;
                float2 r;
                r.x = acc[mt][nt][half * 2 + 0] + bx;
                r.y = acc[mt][nt][half * 2 + 1] + by;
                if (mode == 0) {
                    *(float2*)&out[(size_t)m * N + col] = r;
                } else {
                    const int b  = m >> 11;
                    const int tt = m & (T_ - 1);
                    const int h  = col >> 7;
                    const int dd = col & 127;
                    *(float2*)&out[((size_t)(b * (N >> 7) + h) * T_ + tt) * D_ + dd] = r;
                }
            }
        }
    }
}

__global__ __launch_bounds__(128, 2) void qkv_gemm(
    const float* __restrict__ x,
    const float* __restrict__ wq, const float* __restrict__ bq,
    const float* __restrict__ wk, const float* __restrict__ bk,
    const float* __restrict__ wv, const float* __restrict__ bv,
    float* __restrict__ out_k, float* __restrict__ out_v)
{
    const int bx = blockIdx.x;
    const float* W; const float* bias; float* out; int N; int n0;
    if (bx < 16)      { W = wq; bias = bq; out = (float*)g_q; N = 2048; n0 = bx * 128; }
    else if (bx < 20) { W = wk; bias = bk; out = out_k; N = 512; n0 = (bx - 16) * 128; }
    else              { W = wv; bias = bv; out = out_v; N = 512; n0 = (bx - 20) * 128; }
    gemm_body(x, W, bias, out, N, 1, blockIdx.y * 128, n0);
}

__global__ __launch_bounds__(128, 2) void oproj_gemm(
    const float* __restrict__ wo, float* __restrict__ out)
{
    gemm_body((const float*)g_attn, wo, nullptr, out, 2048, 0,
              blockIdx.y * 128, blockIdx.x * 128);
}

// ---------------------------------------------------------------------------
// RoPE in place, fused q (g_q) + k (out_k): pair (j, j+64)
// ---------------------------------------------------------------------------
#define PQ (B_ * H_ * T_ * 64)
#define PK (B_ * KV_ * T_ * 64)

__global__ void rope_all(float* __restrict__ out_k)
{
    int idx = blockIdx.x * blockDim.x + threadIdx.x;
    float* x;
    if (idx < PQ) { x = (float*)g_q; }
    else          { x = out_k; idx -= PQ; if (idx >= PK) return; }

    const int j = idx & 63;
    const int t = (idx >> 6) & (T_ - 1);
    const int bh = idx >> 17;

    const float freq = expf(-13.815510557964274f * ((float)j / 64.0f));
    const float theta = (float)t * freq;
    const float s = sinf(theta);
    const float c = cosf(theta);

    float* base = x + ((size_t)bh * T_ + t) * D_;
    const float v1 = base[j];
    const float v2 = base[j + 64];
    base[j]      = c * v1 - s * v2;
    base[j + 64] = c * v2 + s * v1;
}

// ---------------------------------------------------------------------------
// Flash attention, tf32 MMA. Q tile 256 rows, 512 threads (16 warps, each
// 16 q-rows). KV tile 64 rows. P staging eliminated via quad-shuffle
// fragment transpose (S accum (g,2t/2t+1) -> A frag (g,t/t+4)).
// smem: Qf 128 KB | Kf 32 KB | Vf 32 KB = 192 KB.
// ---------------------------------------------------------------------------
#define QF_OFF 0
#define KF_OFF 32768
#define VF_OFF 40960
#define FL_SMEM_WORDS 49152   // 192 KB

__global__ __launch_bounds__(512, 1) void flash_mma(
    const float* __restrict__ k, const float* __restrict__ v)
{
    extern __shared__ uint32_t sm[];
    uint32_t* Qf = sm + QF_OFF;
    uint32_t* Kf = sm + KF_OFF;
    uint32_t* Vf = sm + VF_OFF;

    const int tid = threadIdx.x;
    const int lane = tid & 31;
    const int wid = tid >> 5;          // 0..15
    const int g = lane >> 2;
    const int t = lane & 3;

    const int q0 = (int)(gridDim.x - 1 - blockIdx.x) * 256;  // heavy tiles first
    const int h  = blockIdx.y;
    const int b  = blockIdx.z;
    const int kvh = h >> 2;

    const float* qp = (const float*)g_q + ((size_t)(b * H_ + h) * T_ + q0) * D_;
    const float* kp = k + ((size_t)(b * KV_ + kvh) * T_) * D_;
    const float* vp = v + ((size_t)(b * KV_ + kvh) * T_) * D_;

    // ---- load Q tile (256 rows) into fragment layout ----
    {
        const int mrow  = tid >> 1;          // 0..255
        const int dbase = (tid & 1) * 64;
        const int stripe = mrow >> 4;        // 0..15
        const int r  = mrow & 15;
        const int gg = r & 7;
        const int i0 = r >> 3;
        const float* qrow = qp + (size_t)mrow * D_;
#pragma unroll
        for (int it = 0; it < 16; it++) {
            const int d0 = dbase + it * 4;
            float4 q4 = *(const float4*)(qrow + d0);
            float vals[4] = {q4.x, q4.y, q4.z, q4.w};
#pragma unroll
            for (int j = 0; j < 4; j++) {
                const int dd = d0 + j;
                const int c = dd >> 3, u = dd & 7;
                Qf[(((stripe * 16 + c) * 32) + gg * 4 + (u & 3)) * 4 +
                   (i0 | ((u >> 2) << 1))] = f2tf32(vals[j]);
            }
        }
    }

    float acc_o[16][4];
#pragma unroll
    for (int nt = 0; nt < 16; nt++)
#pragma unroll
        for (int i = 0; i < 4; i++) acc_o[nt][i] = 0.0f;

    float m0 = -INFINITY, m1 = -INFINITY, l0 = 0.0f, l1 = 0.0f;
    const float scale = 0.08838834764831845f;  // 1/sqrt(128)

    const int r0 = q0 + wid * 16 + g;
    const int r1 = r0 + 8;
    const int warp_last = q0 + wid * 16 + 15;
    const int ntiles = q0 / 64 + 4;

    // K/V loader indices (512 threads, 64x128 elems each of K and V)
    const int srow = tid >> 3;            // 0..63
    const int dbv  = (tid & 7) * 16;
    const int ntk = srow >> 3;
    const int gk  = srow & 7;
    const int csV = srow >> 3;
    const int usV = srow & 7;
    const int tsV = usV & 3;
    const int hsV = usV >> 2;

    for (int ti = 0; ti < ntiles; ti++) {
        const int s0 = ti * 64;
        __syncthreads();
        {
            const float* krow = kp + (size_t)(s0 + srow) * D_;
            const float* vrow = vp + (size_t)(s0 + srow) * D_;
#pragma unroll
            for (int it = 0; it < 4; it++) {
                const int d0 = dbv + it * 4;
                float4 k4 = *(const float4*)(krow + d0);
                float4 v4 = *(const float4*)(vrow + d0);
                float kv[4] = {k4.x, k4.y, k4.z, k4.w};
                float vv[4] = {v4.x, v4.y, v4.z, v4.w};
#pragma unroll
                for (int j = 0; j < 4; j++) {
                    const int dd = d0 + j;
                    const int ck = dd >> 3, uk = dd & 7;
                    Kf[((ntk * 16 + ck) * 32 + gk * 4 + (uk & 3)) * 2 + (uk >> 2)] =
                        f2tf32(kv[j]);
                    Vf[(((dd >> 3) * 8 + csV) * 32 + (dd & 7) * 4 + tsV) * 2 + hsV] =
                        f2tf32(vv[j]);
                }
            }
        }
        __syncthreads();

        if (s0 > warp_last) continue;   // fully masked for this warp

        // ---- S = Q @ K^T ----
        float accs[8][4];
#pragma unroll
        for (int nt = 0; nt < 8; nt++)
#pragma unroll
            for (int i = 0; i < 4; i++) accs[nt][i] = 0.0f;

#pragma unroll
        for (int c = 0; c < 16; c++) {
            uint4 a = *(const uint4*)&Qf[((wid * 16 + c) * 32 + lane) * 4];
#pragma unroll
            for (int nt = 0; nt < 8; nt++) {
                uint2 bb = *(const uint2*)&Kf[((nt * 16 + c) * 32 + lane) * 2];
                mma_tf32(accs[nt], a.x, a.y, a.z, a.w, bb.x, bb.y);
            }
        }

        // ---- online softmax (mask + scale in place) ----
        float mx0 = -INFINITY, mx1 = -INFINITY;
#pragma unroll
        for (int nt = 0; nt < 8; nt++) {
            const int c0 = s0 + nt * 8 + 2 * t;
            accs[nt][0] = (c0     <= r0) ? accs[nt][0] * scale : -INFINITY;
            accs[nt][1] = (c0 + 1 <= r0) ? accs[nt][1] * scale : -INFINITY;
            accs[nt][2] = (c0     <= r1) ? accs[nt][2] * scale : -INFINITY;
            accs[nt][3] = (c0 + 1 <= r1) ? accs[nt][3] * scale : -INFINITY;
            mx0 = fmaxf(mx0, fmaxf(accs[nt][0], accs[nt][1]));
            mx1 = fmaxf(mx1, fmaxf(accs[nt][2], accs[nt][3]));
        }
        mx0 = fmaxf(mx0, __shfl_xor_sync(0xffffffffu, mx0, 1));
        mx0 = fmaxf(mx0, __shfl_xor_sync(0xffffffffu, mx0, 2));
        mx1 = fmaxf(mx1, __shfl_xor_sync(0xffffffffu, mx1, 1));
        mx1 = fmaxf(mx1, __shfl_xor_sync(0xffffffffu, mx1, 2));

        const float mn0 = fmaxf(m0, mx0);
        const float mn1 = fmaxf(m1, mx1);
        const float corr0 = __expf(m0 - mn0);
        const float corr1 = __expf(m1 - mn1);
        m0 = mn0; m1 = mn1;

        float s0s = 0.0f, s1s = 0.0f;
#pragma unroll
        for (int nt = 0; nt < 8; nt++) {
            accs[nt][0] = __expf(accs[nt][0] - mn0);
            accs[nt][1] = __expf(accs[nt][1] - mn0);
            accs[nt][2] = __expf(accs[nt][2] - mn1);
            accs[nt][3] = __expf(accs[nt][3] - mn1);
            s0s += accs[nt][0] + accs[nt][1];
            s1s += accs[nt][2] + accs[nt][3];
        }
        s0s += __shfl_xor_sync(0xffffffffu, s0s, 1);
        s0s += __shfl_xor_sync(0xffffffffu, s0s, 2);
        s1s += __shfl_xor_sync(0xffffffffu, s1s, 1);
        s1s += __shfl_xor_sync(0xffffffffu, s1s, 2);
        l0 = l0 * corr0 + s0s;
        l1 = l1 * corr1 + s1s;

#pragma unroll
        for (int nt = 0; nt < 16; nt++) {
            acc_o[nt][0] *= corr0; acc_o[nt][1] *= corr0;
            acc_o[nt][2] *= corr1; acc_o[nt][3] *= corr1;
        }

        // ---- O += P @ V : A-fragment built by quad shuffle-transpose ----
        // S accum holds P(g, 2t),(g, 2t+1),(g+8, 2t),(g+8, 2t+1).
        // A frag needs P(g, t),(g+8, t),(g, t+4),(g+8, t+4).
        // Column j lives at quad-lane (j>>1), element (j&1).
#pragma unroll
        for (int c = 0; c < 8; c++) {
            const int src0 = (lane & ~3) | (t >> 1);
            const int src2 = src0 + 2;
            const float e00 = __shfl_sync(0xffffffffu, accs[c][0], src0);
            const float e01 = __shfl_sync(0xffffffffu, accs[c][1], src0);
            const float e10 = __shfl_sync(0xffffffffu, accs[c][2], src0);
            const float e11 = __shfl_sync(0xffffffffu, accs[c][3], src0);
            const float f00 = __shfl_sync(0xffffffffu, accs[c][0], src2);
            const float f01 = __shfl_sync(0xffffffffu, accs[c][1], src2);
            const float f10 = __shfl_sync(0xffffffffu, accs[c][2], src2);
            const float f11 = __shfl_sync(0xffffffffu, accs[c][3], src2);
            const uint32_t a0 = f2tf32((t & 1) ? e01 : e00);  // P(g,   c*8+t)
            const uint32_t a1 = f2tf32((t & 1) ? e11 : e10);  // P(g+8, c*8+t)
            const uint32_t a2 = f2tf32((t & 1) ? f01 : f00);  // P(g,   c*8+t+4)
            const uint32_t a3 = f2tf32((t & 1) ? f11 : f10);  // P(g+8, c*8+t+4)
#pragma unroll
            for (int nt = 0; nt < 16; nt++) {
                uint2 bb = *(const uint2*)&Vf[((nt * 8 + c) * 32 + lane) * 2];
                mma_tf32(acc_o[nt], a0, a1, a2, a3, bb.x, bb.y);
            }
        }
    }

    // ---- epilogue: normalize + write [B,T,H*D] ----
    const float inv0 = 1.0f / l0;
    const float inv1 = 1.0f / l1;
    float* o = (float*)g_attn;
    const size_t ro0 = ((size_t)(b * T_ + r0)) * C_ + h * D_;
    const size_t ro1 = ((size_t)(b * T_ + r1)) * C_ + h * D_;
#pragma unroll
    for (int nt = 0; nt < 16; nt++) {
        const int col = nt * 8 + 2 * t;
        float2 w0, w1;
        w0.x = acc_o[nt][0] * inv0; w0.y = acc_o[nt][1] * inv0;
        w1.x = acc_o[nt][2] * inv1; w1.y = acc_o[nt][3] * inv1;
        *(float2*)&o[ro0 + col] = w0;
        *(float2*)&o[ro1 + col] = w1;
    }
}

// ---------------------------------------------------------------------------
extern "C" void kernel_launch(void* const* d_in, const int* in_sizes, int n_in,
                              void* d_out, int out_size)
{
    const float* x  = (const float*)d_in[0];
    const float* wq = (const float*)d_in[1];
    const float* bq = (const float*)d_in[2];
    const float* wk = (const float*)d_in[3];
    const float* bk = (const float*)d_in[4];
    const float* wv = (const float*)d_in[5];
    const float* bv = (const float*)d_in[6];
    const float* wo = (const float*)d_in[7];

    float* out_main = (float*)d_out;                    // [B,T,C]
    float* out_k = out_main + (size_t)B_ * T_ * C_;     // [B,KV,T,D]
    float* out_v = out_k + (size_t)B_ * KV_ * T_ * D_;  // [B,KV,T,D]

    const int M = B_ * T_;  // 4096

    // Fused QKV projection
    {
        dim3 g(24, M / 128);
        qkv_gemm<<<g, 128>>>(x, wq, bq, wk, bk, wv, bv, out_k, out_v);
    }

    // RoPE on q (g_q) and k (out_k), fused single launch
    {
        const int total = PQ + PK;
        rope_all<<<(total + 255) / 256, 256>>>(out_k);
    }

    // Flash attention (tf32 MMA, 256-row Q tiles, 512 threads)
    {
        const int smem = FL_SMEM_WORDS * (int)sizeof(uint32_t);  // 196608
        cudaFuncSetAttribute(flash_mma,
                             cudaFuncAttributeMaxDynamicSharedMemorySize, smem);
        dim3 g(T_ / 256, H_, B_);
        flash_mma<<<g, 512, smem>>>(out_k, out_v);
    }

    // Output projection
    {
        dim3 go(C_ / 128, M / 128);
        oproj_gemm<<<go, 128>>>(wo, out_main);
    }
}

// round 14
// speedup vs baseline: 1.6610x; 1.0007x over previous
#include <cuda_runtime.h>
#include <math.h>
#include <stdint.h>

#define B_  2
#define T_  2048
#define C_  2048
#define H_  16
#define KV_ 4
#define D_  128
#define REP_ 4
#define KDIM 2048

// Scratch (allocation-free rule: __device__ globals)
__device__ float g_q[B_ * H_ * T_ * D_];     // [B,H,T,D] q (pre/post rope)
__device__ float g_attn[B_ * T_ * H_ * D_];  // [B,T,H*D] attention output rows

// ---------------------------------------------------------------------------
// tf32 helpers
// ---------------------------------------------------------------------------
__device__ __forceinline__ uint32_t f2tf32(float f) {
    uint32_t u;
    asm("cvt.rna.tf32.f32 %0, %1;" : "=r"(u) : "f"(f));
    return u;
}

__device__ __forceinline__ void mma_tf32(float c[4],
                                         uint32_t a0, uint32_t a1, uint32_t a2, uint32_t a3,
                                         uint32_t b0, uint32_t b1) {
    asm volatile(
        "mma.sync.aligned.m16n8k8.row.col.f32.tf32.tf32.f32 "
        "{%0,%1,%2,%3}, {%4,%5,%6,%7}, {%8,%9}, {%0,%1,%2,%3};"
        : "+f"(c[0]), "+f"(c[1]), "+f"(c[2]), "+f"(c[3])
        : "r"(a0), "r"(a1), "r"(a2), "r"(a3), "r"(b0), "r"(b1));
}

// ---------------------------------------------------------------------------
// tf32 GEMM, 64x64 warp tiles (r9-proven): out = A[M,2048] @ W[2048,N] (+bias)
// ---------------------------------------------------------------------------
#define SA 20
#define SB 136

__device__ __forceinline__ void gemm_body(
    const float* __restrict__ A, const float* __restrict__ W,
    const float* __restrict__ bias, float* __restrict__ out,
    int N, int mode, int m0, int n0)
{
    __shared__ uint32_t As[128 * SA];
    __shared__ uint32_t Bs[16 * SB];

    const int tid  = threadIdx.x;          // 0..127
    const int wid  = tid >> 5;             // 0..3
    const int lane = tid & 31;
    const int g = lane >> 2;
    const int t = lane & 3;
    const int warp_m = (wid & 1) * 64;
    const int warp_n = (wid >> 1) * 64;

    float acc[4][8][4];
#pragma unroll
    for (int mt = 0; mt < 4; mt++)
#pragma unroll
        for (int nt = 0; nt < 8; nt++)
#pragma unroll
            for (int i = 0; i < 4; i++) acc[mt][nt][i] = 0.0f;

    const int aRow = tid >> 2;
    const int aCol = (tid & 3) * 4;
    const int bRow = tid >> 5;
    const int bCol = (tid & 31) * 4;

    const float* pa = A + (size_t)(m0 + aRow) * KDIM + aCol;
    const float* pb = W + (size_t)bRow * N + n0 + bCol;

    float4 av[4], bv[4];
#pragma unroll
    for (int c = 0; c < 4; c++) {
        av[c] = *(const float4*)(pa + (size_t)(32 * c) * KDIM);
        bv[c] = *(const float4*)(pb + (size_t)(4 * c) * N);
    }

    for (int k0 = 0; k0 < KDIM; k0 += 16) {
        __syncthreads();
#pragma unroll
        for (int c = 0; c < 4; c++) {
            uint32_t* qa = &As[(aRow + 32 * c) * SA + aCol];
            qa[0] = f2tf32(av[c].x); qa[1] = f2tf32(av[c].y);
            qa[2] = f2tf32(av[c].z); qa[3] = f2tf32(av[c].w);
            uint32_t* qb = &Bs[(bRow + 4 * c) * SB + bCol];
            qb[0] = f2tf32(bv[c].x); qb[1] = f2tf32(bv[c].y);
            qb[2] = f2tf32(bv[c].z); qb[3] = f2tf32(bv[c].w);
        }
        __syncthreads();

        if (k0 + 16 < KDIM) {
            pa += 16;
            pb += (size_t)16 * N;
#pragma unroll
            for (int c = 0; c < 4; c++) {
                av[c] = *(const float4*)(pa + (size_t)(32 * c) * KDIM);
                bv[c] = *(const float4*)(pb + (size_t)(4 * c) * N);
            }
        }

#pragma unroll
        for (int kk = 0; kk < 16; kk += 8) {
            uint32_t afr[4][4];
#pragma unroll
            for (int mt = 0; mt < 4; mt++) {
                const int rb = warp_m + mt * 16;
                afr[mt][0] = As[(rb + g)     * SA + kk + t];
                afr[mt][1] = As[(rb + g + 8) * SA + kk + t];
                afr[mt][2] = As[(rb + g)     * SA + kk + t + 4];
                afr[mt][3] = As[(rb + g + 8) * SA + kk + t + 4];
            }
            uint32_t bfr[8][2];
#pragma unroll
            for (int nt = 0; nt < 8; nt++) {
                const int cn = warp_n + nt * 8 + g;
                bfr[nt][0] = Bs[(kk + t)     * SB + cn];
                bfr[nt][1] = Bs[(kk + t + 4) * SB + cn];
            }
#pragma unroll
            for (int mt = 0; mt < 4; mt++)
#pragma unroll
                for (int nt = 0; nt < 8; nt++)
                    mma_tf32(acc[mt][nt],
                             afr[mt][0], afr[mt][1], afr[mt][2], afr[mt][3],
                             bfr[nt][0], bfr[nt][1]);
        }
    }

#pragma unroll
    for (int mt = 0; mt < 4; mt++) {
#pragma unroll
        for (int nt = 0; nt < 8; nt++) {
            const int col = n0 + warp_n + nt * 8 + 2 * t;
            float bx = 0.0f, by = 0.0f;
            if (bias) { bx = bias[col]; by = bias[col + 1]; }
#pragma unroll
            for (int half = 0; half < 2; half++) {
                const int m = m0 + warp_m + mt * 16 + g + half * 8;
                float2 r;
                r.x = acc[mt][nt][half * 2 + 0] + bx;
                r.y = acc[mt][nt][half * 2 + 1] + by;
                if (mode == 0) {
                    *(float2*)&out[(size_t)m * N + col] = r;
                } else {
                    const int b  = m >> 11;
                    const int tt = m & (T_ - 1);
                    const int h  = col >> 7;
                    const int dd = col & 127;
                    *(float2*)&out[((size_t)(b * (N >> 7) + h) * T_ + tt) * D_ + dd] = r;
                }
            }
        }
    }
}

__global__ __launch_bounds__(128, 2) void qkv_gemm(
    const float* __restrict__ x,
    const float* __restrict__ wq, const float* __restrict__ bq,
    const float* __restrict__ wk, const float* __restrict__ bk,
    const float* __restrict__ wv, const float* __restrict__ bv,
    float* __restrict__ out_k, float* __restrict__ out_v)
{
    const int bx = blockIdx.x;
    const float* W; const float* bias; float* out; int N; int n0;
    if (bx < 16)      { W = wq; bias = bq; out = (float*)g_q; N = 2048; n0 = bx * 128; }
    else if (bx < 20) { W = wk; bias = bk; out = out_k; N = 512; n0 = (bx - 16) * 128; }
    else              { W = wv; bias = bv; out = out_v; N = 512; n0 = (bx - 20) * 128; }
    gemm_body(x, W, bias, out, N, 1, blockIdx.y * 128, n0);
}

__global__ __launch_bounds__(128, 2) void oproj_gemm(
    const float* __restrict__ wo, float* __restrict__ out)
{
    gemm_body((const float*)g_attn, wo, nullptr, out, 2048, 0,
              blockIdx.y * 128, blockIdx.x * 128);
}

// ---------------------------------------------------------------------------
// RoPE in place, fused q (g_q) + k (out_k): pair (j, j+64)
// ---------------------------------------------------------------------------
#define PQ (B_ * H_ * T_ * 64)
#define PK (B_ * KV_ * T_ * 64)

__global__ void rope_all(float* __restrict__ out_k)
{
    int idx = blockIdx.x * blockDim.x + threadIdx.x;
    float* x;
    if (idx < PQ) { x = (float*)g_q; }
    else          { x = out_k; idx -= PQ; if (idx >= PK) return; }

    const int j = idx & 63;
    const int t = (idx >> 6) & (T_ - 1);
    const int bh = idx >> 17;

    const float freq = expf(-13.815510557964274f * ((float)j / 64.0f));
    const float theta = (float)t * freq;
    const float s = sinf(theta);
    const float c = cosf(theta);

    float* base = x + ((size_t)bh * T_ + t) * D_;
    const float v1 = base[j];
    const float v2 = base[j + 64];
    base[j]      = c * v1 - s * v2;
    base[j + 64] = c * v2 + s * v1;
}

// ---------------------------------------------------------------------------
// Flash attention, tf32 MMA. Q tile 256 rows, 512 threads (16 warps, each
// 16 q-rows). KV tile 64 rows. P staging eliminated via quad-shuffle
// fragment transpose (S accum (g,2t/2t+1) -> A frag (g,t/t+4)).
// smem: Qf 128 KB | Kf 32 KB | Vf 32 KB = 192 KB.
// ---------------------------------------------------------------------------
#define QF_OFF 0
#define KF_OFF 32768
#define VF_OFF 40960
#define FL_SMEM_WORDS 49152   // 192 KB

__global__ __launch_bounds__(512, 1) void flash_mma(
    const float* __restrict__ k, const float* __restrict__ v)
{
    extern __shared__ uint32_t sm[];
    uint32_t* Qf = sm + QF_OFF;
    uint32_t* Kf = sm + KF_OFF;
    uint32_t* Vf = sm + VF_OFF;

    const int tid = threadIdx.x;
    const int lane = tid & 31;
    const int wid = tid >> 5;          // 0..15
    const int g = lane >> 2;
    const int t = lane & 3;

    const int q0 = (int)(gridDim.x - 1 - blockIdx.x) * 256;  // heavy tiles first
    const int h  = blockIdx.y;
    const int b  = blockIdx.z;
    const int kvh = h >> 2;

    const float* qp = (const float*)g_q + ((size_t)(b * H_ + h) * T_ + q0) * D_;
    const float* kp = k + ((size_t)(b * KV_ + kvh) * T_) * D_;
    const float* vp = v + ((size_t)(b * KV_ + kvh) * T_) * D_;

    // ---- load Q tile (256 rows) into fragment layout ----
    {
        const int mrow  = tid >> 1;          // 0..255
        const int dbase = (tid & 1) * 64;
        const int stripe = mrow >> 4;        // 0..15
        const int r  = mrow & 15;
        const int gg = r & 7;
        const int i0 = r >> 3;
        const float* qrow = qp + (size_t)mrow * D_;
#pragma unroll
        for (int it = 0; it < 16; it++) {
            const int d0 = dbase + it * 4;
            float4 q4 = *(const float4*)(qrow + d0);
            float vals[4] = {q4.x, q4.y, q4.z, q4.w};
#pragma unroll
            for (int j = 0; j < 4; j++) {
                const int dd = d0 + j;
                const int c = dd >> 3, u = dd & 7;
                Qf[(((stripe * 16 + c) * 32) + gg * 4 + (u & 3)) * 4 +
                   (i0 | ((u >> 2) << 1))] = f2tf32(vals[j]);
            }
        }
    }

    float acc_o[16][4];
#pragma unroll
    for (int nt = 0; nt < 16; nt++)
#pragma unroll
        for (int i = 0; i < 4; i++) acc_o[nt][i] = 0.0f;

    float m0 = -INFINITY, m1 = -INFINITY, l0 = 0.0f, l1 = 0.0f;
    const float scale = 0.08838834764831845f;  // 1/sqrt(128)

    const int r0 = q0 + wid * 16 + g;
    const int r1 = r0 + 8;
    const int warp_last = q0 + wid * 16 + 15;
    const int ntiles = q0 / 64 + 4;

    // K/V loader indices (512 threads, 64x128 elems each of K and V)
    const int srow = tid >> 3;            // 0..63
    const int dbv  = (tid & 7) * 16;
    const int ntk = srow >> 3;
    const int gk  = srow & 7;
    const int csV = srow >> 3;
    const int usV = srow & 7;
    const int tsV = usV & 3;
    const int hsV = usV >> 2;

    for (int ti = 0; ti < ntiles; ti++) {
        const int s0 = ti * 64;
        __syncthreads();
        {
            const float* krow = kp + (size_t)(s0 + srow) * D_;
            const float* vrow = vp + (size_t)(s0 + srow) * D_;
#pragma unroll
            for (int it = 0; it < 4; it++) {
                const int d0 = dbv + it * 4;
                float4 k4 = *(const float4*)(krow + d0);
                float4 v4 = *(const float4*)(vrow + d0);
                float kv[4] = {k4.x, k4.y, k4.z, k4.w};
                float vv[4] = {v4.x, v4.y, v4.z, v4.w};
#pragma unroll
                for (int j = 0; j < 4; j++) {
                    const int dd = d0 + j;
                    const int ck = dd >> 3, uk = dd & 7;
                    Kf[((ntk * 16 + ck) * 32 + gk * 4 + (uk & 3)) * 2 + (uk >> 2)] =
                        f2tf32(kv[j]);
                    Vf[(((dd >> 3) * 8 + csV) * 32 + (dd & 7) * 4 + tsV) * 2 + hsV] =
                        f2tf32(vv[j]);
                }
            }
        }
        __syncthreads();

        if (s0 > warp_last) continue;   // fully masked for this warp

        // ---- S = Q @ K^T ----
        float accs[8][4];
#pragma unroll
        for (int nt = 0; nt < 8; nt++)
#pragma unroll
            for (int i = 0; i < 4; i++) accs[nt][i] = 0.0f;

#pragma unroll
        for (int c = 0; c < 16; c++) {
            uint4 a = *(const uint4*)&Qf[((wid * 16 + c) * 32 + lane) * 4];
#pragma unroll
            for (int nt = 0; nt < 8; nt++) {
                uint2 bb = *(const uint2*)&Kf[((nt * 16 + c) * 32 + lane) * 2];
                mma_tf32(accs[nt], a.x, a.y, a.z, a.w, bb.x, bb.y);
            }
        }

        // ---- online softmax (mask + scale in place) ----
        float mx0 = -INFINITY, mx1 = -INFINITY;
#pragma unroll
        for (int nt = 0; nt < 8; nt++) {
            const int c0 = s0 + nt * 8 + 2 * t;
            accs[nt][0] = (c0     <= r0) ? accs[nt][0] * scale : -INFINITY;
            accs[nt][1] = (c0 + 1 <= r0) ? accs[nt][1] * scale : -INFINITY;
            accs[nt][2] = (c0     <= r1) ? accs[nt][2] * scale : -INFINITY;
            accs[nt][3] = (c0 + 1 <= r1) ? accs[nt][3] * scale : -INFINITY;
            mx0 = fmaxf(mx0, fmaxf(accs[nt][0], accs[nt][1]));
            mx1 = fmaxf(mx1, fmaxf(accs[nt][2], accs[nt][3]));
        }
        mx0 = fmaxf(mx0, __shfl_xor_sync(0xffffffffu, mx0, 1));
        mx0 = fmaxf(mx0, __shfl_xor_sync(0xffffffffu, mx0, 2));
        mx1 = fmaxf(mx1, __shfl_xor_sync(0xffffffffu, mx1, 1));
        mx1 = fmaxf(mx1, __shfl_xor_sync(0xffffffffu, mx1, 2));

        const float mn0 = fmaxf(m0, mx0);
        const float mn1 = fmaxf(m1, mx1);
        const float corr0 = __expf(m0 - mn0);
        const float corr1 = __expf(m1 - mn1);
        m0 = mn0; m1 = mn1;

        float s0s = 0.0f, s1s = 0.0f;
#pragma unroll
        for (int nt = 0; nt < 8; nt++) {
            accs[nt][0] = __expf(accs[nt][0] - mn0);
            accs[nt][1] = __expf(accs[nt][1] - mn0);
            accs[nt][2] = __expf(accs[nt][2] - mn1);
            accs[nt][3] = __expf(accs[nt][3] - mn1);
            s0s += accs[nt][0] + accs[nt][1];
            s1s += accs[nt][2] + accs[nt][3];
        }
        s0s += __shfl_xor_sync(0xffffffffu, s0s, 1);
        s0s += __shfl_xor_sync(0xffffffffu, s0s, 2);
        s1s += __shfl_xor_sync(0xffffffffu, s1s, 1);
        s1s += __shfl_xor_sync(0xffffffffu, s1s, 2);
        l0 = l0 * corr0 + s0s;
        l1 = l1 * corr1 + s1s;

#pragma unroll
        for (int nt = 0; nt < 16; nt++) {
            acc_o[nt][0] *= corr0; acc_o[nt][1] *= corr0;
            acc_o[nt][2] *= corr1; acc_o[nt][3] *= corr1;
        }

        // ---- O += P @ V : A-fragment built by quad shuffle-transpose ----
        // S accum holds P(g, 2t),(g, 2t+1),(g+8, 2t),(g+8, 2t+1).
        // A frag needs P(g, t),(g+8, t),(g, t+4),(g+8, t+4).
        // Column j lives at quad-lane (j>>1), element (j&1).
#pragma unroll
        for (int c = 0; c < 8; c++) {
            const int src0 = (lane & ~3) | (t >> 1);
            const int src2 = src0 + 2;
            const float e00 = __shfl_sync(0xffffffffu, accs[c][0], src0);
            const float e01 = __shfl_sync(0xffffffffu, accs[c][1], src0);
            const float e10 = __shfl_sync(0xffffffffu, accs[c][2], src0);
            const float e11 = __shfl_sync(0xffffffffu, accs[c][3], src0);
            const float f00 = __shfl_sync(0xffffffffu, accs[c][0], src2);
            const float f01 = __shfl_sync(0xffffffffu, accs[c][1], src2);
            const float f10 = __shfl_sync(0xffffffffu, accs[c][2], src2);
            const float f11 = __shfl_sync(0xffffffffu, accs[c][3], src2);
            const uint32_t a0 = f2tf32((t & 1) ? e01 : e00);  // P(g,   c*8+t)
            const uint32_t a1 = f2tf32((t & 1) ? e11 : e10);  // P(g+8, c*8+t)
            const uint32_t a2 = f2tf32((t & 1) ? f01 : f00);  // P(g,   c*8+t+4)
            const uint32_t a3 = f2tf32((t & 1) ? f11 : f10);  // P(g+8, c*8+t+4)
#pragma unroll
            for (int nt = 0; nt < 16; nt++) {
                uint2 bb = *(const uint2*)&Vf[((nt * 8 + c) * 32 + lane) * 2];
                mma_tf32(acc_o[nt], a0, a1, a2, a3, bb.x, bb.y);
            }
        }
    }

    // ---- epilogue: normalize + write [B,T,H*D] ----
    const float inv0 = 1.0f / l0;
    const float inv1 = 1.0f / l1;
    float* o = (float*)g_attn;
    const size_t ro0 = ((size_t)(b * T_ + r0)) * C_ + h * D_;
    const size_t ro1 = ((size_t)(b * T_ + r1)) * C_ + h * D_;
#pragma unroll
    for (int nt = 0; nt < 16; nt++) {
        const int col = nt * 8 + 2 * t;
        float2 w0, w1;
        w0.x = acc_o[nt][0] * inv0; w0.y = acc_o[nt][1] * inv0;
        w1.x = acc_o[nt][2] * inv1; w1.y = acc_o[nt][3] * inv1;
        *(float2*)&o[ro0 + col] = w0;
        *(float2*)&o[ro1 + col] = w1;
    }
}

// ---------------------------------------------------------------------------
extern "C" void kernel_launch(void* const* d_in, const int* in_sizes, int n_in,
                              void* d_out, int out_size)
{
    const float* x  = (const float*)d_in[0];
    const float* wq = (const float*)d_in[1];
    const float* bq = (const float*)d_in[2];
    const float* wk = (const float*)d_in[3];
    const float* bk = (const float*)d_in[4];
    const float* wv = (const float*)d_in[5];
    const float* bv = (const float*)d_in[6];
    const float* wo = (const float*)d_in[7];

    float* out_main = (float*)d_out;                    // [B,T,C]
    float* out_k = out_main + (size_t)B_ * T_ * C_;     // [B,KV,T,D]
    float* out_v = out_k + (size_t)B_ * KV_ * T_ * D_;  // [B,KV,T,D]

    const int M = B_ * T_;  // 4096

    // Fused QKV projection
    {
        dim3 g(24, M / 128);
        qkv_gemm<<<g, 128>>>(x, wq, bq, wk, bk, wv, bv, out_k, out_v);
    }

    // RoPE on q (g_q) and k (out_k), fused single launch
    {
        const int total = PQ + PK;
        rope_all<<<(total + 255) / 256, 256>>>(out_k);
    }

    // Flash attention (tf32 MMA, 256-row Q tiles, 512 threads)
    {
        const int smem = FL_SMEM_WORDS * (int)sizeof(uint32_t);  // 196608
        cudaFuncSetAttribute(flash_mma,
                             cudaFuncAttributeMaxDynamicSharedMemorySize, smem);
        dim3 g(T_ / 256, H_, B_);
        flash_mma<<<g, 512, smem>>>(out_k, out_v);
    }

    // Output projection
    {
        dim3 go(C_ / 128, M / 128);
        oproj_gemm<<<go, 128>>>(wo, out_main);
    }
}

// round 15
// speedup vs baseline: 1.8443x; 1.1104x over previous
#include <cuda_runtime.h>
#include <math.h>
#include <stdint.h>

#define B_  2
#define T_  2048
#define C_  2048
#define H_  16
#define KV_ 4
#define D_  128
#define REP_ 4
#define KDIM 2048

// Scratch (allocation-free rule: __device__ globals)
__device__ float g_q[B_ * H_ * T_ * D_];     // [B,H,T,D] q (pre/post rope)
__device__ float g_attn[B_ * T_ * H_ * D_];  // [B,T,H*D] attention output rows

// ---------------------------------------------------------------------------
// tf32 helpers
// ---------------------------------------------------------------------------
__device__ __forceinline__ uint32_t f2tf32(float f) {
    uint32_t u;
    asm("cvt.rna.tf32.f32 %0, %1;" : "=r"(u) : "f"(f));
    return u;
}

__device__ __forceinline__ void mma_tf32(float c[4],
                                         uint32_t a0, uint32_t a1, uint32_t a2, uint32_t a3,
                                         uint32_t b0, uint32_t b1) {
    asm volatile(
        "mma.sync.aligned.m16n8k8.row.col.f32.tf32.tf32.f32 "
        "{%0,%1,%2,%3}, {%4,%5,%6,%7}, {%8,%9}, {%0,%1,%2,%3};"
        : "+f"(c[0]), "+f"(c[1]), "+f"(c[2]), "+f"(c[3])
        : "r"(a0), "r"(a1), "r"(a2), "r"(a3), "r"(b0), "r"(b1));
}

__device__ __forceinline__ uint32_t smem_u32(const void* p) {
    uint32_t a;
    asm("{ .reg .u64 t; cvta.to.shared.u64 t, %1; cvt.u32.u64 %0, t; }" : "=r"(a) : "l"(p));
    return a;
}

__device__ __forceinline__ void cpa16(uint32_t dst, const float* src) {
    asm volatile("cp.async.cg.shared.global [%0], [%1], 16;" :: "r"(dst), "l"(src));
}
#define CP_COMMIT() asm volatile("cp.async.commit_group;" ::: "memory")
#define CP_WAIT0()  asm volatile("cp.async.wait_group 0;" ::: "memory")

// ---------------------------------------------------------------------------
// tf32 GEMM, 64x64 warp tiles (r9-proven): out = A[M,2048] @ W[2048,N] (+bias)
// ---------------------------------------------------------------------------
#define SA 20
#define SB 136

__device__ __forceinline__ void gemm_body(
    const float* __restrict__ A, const float* __restrict__ W,
    const float* __restrict__ bias, float* __restrict__ out,
    int N, int mode, int m0, int n0)
{
    __shared__ uint32_t As[128 * SA];
    __shared__ uint32_t Bs[16 * SB];

    const int tid  = threadIdx.x;          // 0..127
    const int wid  = tid >> 5;             // 0..3
    const int lane = tid & 31;
    const int g = lane >> 2;
    const int t = lane & 3;
    const int warp_m = (wid & 1) * 64;
    const int warp_n = (wid >> 1) * 64;

    float acc[4][8][4];
#pragma unroll
    for (int mt = 0; mt < 4; mt++)
#pragma unroll
        for (int nt = 0; nt < 8; nt++)
#pragma unroll
            for (int i = 0; i < 4; i++) acc[mt][nt][i] = 0.0f;

    const int aRow = tid >> 2;
    const int aCol = (tid & 3) * 4;
    const int bRow = tid >> 5;
    const int bCol = (tid & 31) * 4;

    const float* pa = A + (size_t)(m0 + aRow) * KDIM + aCol;
    const float* pb = W + (size_t)bRow * N + n0 + bCol;

    float4 av[4], bv[4];
#pragma unroll
    for (int c = 0; c < 4; c++) {
        av[c] = *(const float4*)(pa + (size_t)(32 * c) * KDIM);
        bv[c] = *(const float4*)(pb + (size_t)(4 * c) * N);
    }

    for (int k0 = 0; k0 < KDIM; k0 += 16) {
        __syncthreads();
#pragma unroll
        for (int c = 0; c < 4; c++) {
            uint32_t* qa = &As[(aRow + 32 * c) * SA + aCol];
            qa[0] = f2tf32(av[c].x); qa[1] = f2tf32(av[c].y);
            qa[2] = f2tf32(av[c].z); qa[3] = f2tf32(av[c].w);
            uint32_t* qb = &Bs[(bRow + 4 * c) * SB + bCol];
            qb[0] = f2tf32(bv[c].x); qb[1] = f2tf32(bv[c].y);
            qb[2] = f2tf32(bv[c].z); qb[3] = f2tf32(bv[c].w);
        }
        __syncthreads();

        if (k0 + 16 < KDIM) {
            pa += 16;
            pb += (size_t)16 * N;
#pragma unroll
            for (int c = 0; c < 4; c++) {
                av[c] = *(const float4*)(pa + (size_t)(32 * c) * KDIM);
                bv[c] = *(const float4*)(pb + (size_t)(4 * c) * N);
            }
        }

#pragma unroll
        for (int kk = 0; kk < 16; kk += 8) {
            uint32_t afr[4][4];
#pragma unroll
            for (int mt = 0; mt < 4; mt++) {
                const int rb = warp_m + mt * 16;
                afr[mt][0] = As[(rb + g)     * SA + kk + t];
                afr[mt][1] = As[(rb + g + 8) * SA + kk + t];
                afr[mt][2] = As[(rb + g)     * SA + kk + t + 4];
                afr[mt][3] = As[(rb + g + 8) * SA + kk + t + 4];
            }
            uint32_t bfr[8][2];
#pragma unroll
            for (int nt = 0; nt < 8; nt++) {
                const int cn = warp_n + nt * 8 + g;
                bfr[nt][0] = Bs[(kk + t)     * SB + cn];
                bfr[nt][1] = Bs[(kk + t + 4) * SB + cn];
            }
#pragma unroll
            for (int mt = 0; mt < 4; mt++)
#pragma unroll
                for (int nt = 0; nt < 8; nt++)
                    mma_tf32(acc[mt][nt],
                             afr[mt][0], afr[mt][1], afr[mt][2], afr[mt][3],
                             bfr[nt][0], bfr[nt][1]);
        }
    }

#pragma unroll
    for (int mt = 0; mt < 4; mt++) {
#pragma unroll
        for (int nt = 0; nt < 8; nt++) {
            const int col = n0 + warp_n + nt * 8 + 2 * t;
            float bx = 0.0f, by = 0.0f;
            if (bias) { bx = bias[col]; by = bias[col + 1]; }
#pragma unroll
            for (int half = 0; half < 2; half++) {
                const int m = m0 + warp_m + mt * 16 + g + half * 8;
                float2 r;
                r.x = acc[mt][nt][half * 2 + 0] + bx;
                r.y = acc[mt][nt][half * 2 + 1] + by;
                if (mode == 0) {
                    *(float2*)&out[(size_t)m * N + col] = r;
                } else {
                    const int b  = m >> 11;
                    const int tt = m & (T_ - 1);
                    const int h  = col >> 7;
                    const int dd = col & 127;
                    *(float2*)&out[((size_t)(b * (N >> 7) + h) * T_ + tt) * D_ + dd] = r;
                }
            }
        }
    }
}

__global__ __launch_bounds__(128, 2) void qkv_gemm(
    const float* __restrict__ x,
    const float* __restrict__ wq, const float* __restrict__ bq,
    const float* __restrict__ wk, const float* __restrict__ bk,
    const float* __restrict__ wv, const float* __restrict__ bv,
    float* __restrict__ out_k, float* __restrict__ out_v)
{
    const int bx = blockIdx.x;
    const float* W; const float* bias; float* out; int N; int n0;
    if (bx < 16)      { W = wq; bias = bq; out = (float*)g_q; N = 2048; n0 = bx * 128; }
    else if (bx < 20) { W = wk; bias = bk; out = out_k; N = 512; n0 = (bx - 16) * 128; }
    else              { W = wv; bias = bv; out = out_v; N = 512; n0 = (bx - 20) * 128; }
    gemm_body(x, W, bias, out, N, 1, blockIdx.y * 128, n0);
}

__global__ __launch_bounds__(128, 2) void oproj_gemm(
    const float* __restrict__ wo, float* __restrict__ out)
{
    gemm_body((const float*)g_attn, wo, nullptr, out, 2048, 0,
              blockIdx.y * 128, blockIdx.x * 128);
}

// ---------------------------------------------------------------------------
// RoPE in place, fused q (g_q) + k (out_k): pair (j, j+64)
// ---------------------------------------------------------------------------
#define PQ (B_ * H_ * T_ * 64)
#define PK (B_ * KV_ * T_ * 64)

__global__ void rope_all(float* __restrict__ out_k)
{
    int idx = blockIdx.x * blockDim.x + threadIdx.x;
    float* x;
    if (idx < PQ) { x = (float*)g_q; }
    else          { x = out_k; idx -= PQ; if (idx >= PK) return; }

    const int j = idx & 63;
    const int t = (idx >> 6) & (T_ - 1);
    const int bh = idx >> 17;

    const float freq = expf(-13.815510557964274f * ((float)j / 64.0f));
    const float theta = (float)t * freq;
    const float s = sinf(theta);
    const float c = cosf(theta);

    float* base = x + ((size_t)bh * T_ + t) * D_;
    const float v1 = base[j];
    const float v2 = base[j + 64];
    base[j]      = c * v1 - s * v2;
    base[j + 64] = c * v2 + s * v1;
}

// ---------------------------------------------------------------------------
// Flash attention, tf32 MMA, cp.async-pipelined K/V, Q in registers.
// 256 threads (8 warps x 16 q-rows), Q tile 128 rows, KV tile 64 rows.
// smem words: Kf 8192 | Vf 8192 | raw 16384 (K 8192 + V 8192; also Q staging)
// = 32768 words = 128 KB, 1 CTA/SM, 256-reg budget (no spills).
// Pipeline: cp.async(ti+1) flies during compute(ti); convert smem->frag after.
// ---------------------------------------------------------------------------
#define KF_W  0
#define VF_W  8192
#define RAW_W 16384
#define FL_SMEM_BYTES (32768 * 4)

__device__ __forceinline__ void kv_issue(uint32_t raw_addr,
                                         const float* ks, const float* vs, int tid)
{
#pragma unroll
    for (int i = 0; i < 8; i++) {
        const int off = (i * 256 + tid) * 4;
        cpa16(raw_addr + off * 4, ks + off);
        cpa16(raw_addr + 32768 + off * 4, vs + off);
    }
    CP_COMMIT();
}

__device__ __forceinline__ void kv_convert(uint32_t* sm, int wid, int lane)
{
    const float* rk = (const float*)(sm + RAW_W);
    const float* rv = (const float*)(sm + RAW_W + 8192);
    uint32_t* Kf = sm + KF_W;
    uint32_t* Vf = sm + VF_W;
#pragma unroll
    for (int j = 0; j < 8; j++) {
        const int r = wid * 8 + j;           // kv row 0..63
        const int ntk = r >> 3, gk = r & 7;
        const int csV = r >> 3, tsV = j & 3, hsV = j >> 2;
#pragma unroll
        for (int c = 0; c < 4; c++) {
            const int dd = lane + 32 * c;    // d col, conflict-free reads
            const int ck = dd >> 3, uk = dd & 7;
            Kf[((ntk * 16 + ck) * 32 + gk * 4 + (uk & 3)) * 2 + (uk >> 2)] =
                f2tf32(rk[r * 128 + dd]);
            const int ntv = dd >> 3, gv = dd & 7;
            Vf[((ntv * 8 + csV) * 32 + gv * 4 + tsV) * 2 + hsV] =
                f2tf32(rv[r * 128 + dd]);
        }
    }
}

__global__ __launch_bounds__(256, 1) void flash_mma(
    const float* __restrict__ k, const float* __restrict__ v)
{
    extern __shared__ uint32_t sm[];
    uint32_t* Kf = sm + KF_W;
    uint32_t* Vf = sm + VF_W;

    const int tid = threadIdx.x;
    const int lane = tid & 31;
    const int wid = tid >> 5;          // 0..7
    const int g = lane >> 2;
    const int t = lane & 3;

    const int q0 = (int)(gridDim.x - 1 - blockIdx.x) * 128;  // heavy tiles first
    const int h  = blockIdx.y;
    const int b  = blockIdx.z;
    const int kvh = h >> 2;

    const float* qp = (const float*)g_q + ((size_t)(b * H_ + h) * T_ + q0) * D_;
    const float* kp = k + ((size_t)(b * KV_ + kvh) * T_) * D_;
    const float* vp = v + ((size_t)(b * KV_ + kvh) * T_) * D_;

    const uint32_t sbase = smem_u32(sm);
    const uint32_t raw_addr = sbase + RAW_W * 4;

    // ---- stage Q tile (128x128 = 64 KB) into raw region via cp.async ----
#pragma unroll
    for (int i = 0; i < 16; i++) {
        const int off = (i * 256 + tid) * 4;
        cpa16(raw_addr + off * 4, qp + off);
    }
    CP_COMMIT();
    CP_WAIT0();
    __syncthreads();

    // ---- Q fragments into registers (64 regs) ----
    uint32_t qa[16][4];
    {
        const float* qstage = (const float*)(sm + RAW_W);
        const int R0 = wid * 16 + g, R1 = R0 + 8;
#pragma unroll
        for (int c = 0; c < 16; c++) {
            qa[c][0] = f2tf32(qstage[R0 * 128 + c * 8 + t]);
            qa[c][1] = f2tf32(qstage[R1 * 128 + c * 8 + t]);
            qa[c][2] = f2tf32(qstage[R0 * 128 + c * 8 + t + 4]);
            qa[c][3] = f2tf32(qstage[R1 * 128 + c * 8 + t + 4]);
        }
    }
    __syncthreads();

    float acc_o[16][4];
#pragma unroll
    for (int nt = 0; nt < 16; nt++)
#pragma unroll
        for (int i = 0; i < 4; i++) acc_o[nt][i] = 0.0f;

    float m0 = -INFINITY, m1 = -INFINITY, l0 = 0.0f, l1 = 0.0f;
    const float scale = 0.08838834764831845f;  // 1/sqrt(128)

    const int r0 = q0 + wid * 16 + g;
    const int r1 = r0 + 8;
    const int warp_last = q0 + wid * 16 + 15;
    const int ntiles = q0 / 64 + 2;

    // ---- prologue: tile 0 ----
    kv_issue(raw_addr, kp, vp, tid);
    CP_WAIT0();
    __syncthreads();
    kv_convert(sm, wid, lane);
    __syncthreads();
    if (ntiles > 1) kv_issue(raw_addr, kp + 64 * 128, vp + 64 * 128, tid);

    for (int ti = 0; ti < ntiles; ti++) {
        const int s0 = ti * 64;

        if (s0 <= warp_last) {
            // ---- S = Q @ K^T (Q from registers) ----
            float accs[8][4];
#pragma unroll
            for (int nt = 0; nt < 8; nt++)
#pragma unroll
                for (int i = 0; i < 4; i++) accs[nt][i] = 0.0f;

#pragma unroll
            for (int c = 0; c < 16; c++) {
#pragma unroll
                for (int nt = 0; nt < 8; nt++) {
                    uint2 bb = *(const uint2*)&Kf[((nt * 16 + c) * 32 + lane) * 2];
                    mma_tf32(accs[nt], qa[c][0], qa[c][1], qa[c][2], qa[c][3],
                             bb.x, bb.y);
                }
            }

            // ---- online softmax ----
            float mx0 = -INFINITY, mx1 = -INFINITY;
#pragma unroll
            for (int nt = 0; nt < 8; nt++) {
                const int c0 = s0 + nt * 8 + 2 * t;
                accs[nt][0] = (c0     <= r0) ? accs[nt][0] * scale : -INFINITY;
                accs[nt][1] = (c0 + 1 <= r0) ? accs[nt][1] * scale : -INFINITY;
                accs[nt][2] = (c0     <= r1) ? accs[nt][2] * scale : -INFINITY;
                accs[nt][3] = (c0 + 1 <= r1) ? accs[nt][3] * scale : -INFINITY;
                mx0 = fmaxf(mx0, fmaxf(accs[nt][0], accs[nt][1]));
                mx1 = fmaxf(mx1, fmaxf(accs[nt][2], accs[nt][3]));
            }
            mx0 = fmaxf(mx0, __shfl_xor_sync(0xffffffffu, mx0, 1));
            mx0 = fmaxf(mx0, __shfl_xor_sync(0xffffffffu, mx0, 2));
            mx1 = fmaxf(mx1, __shfl_xor_sync(0xffffffffu, mx1, 1));
            mx1 = fmaxf(mx1, __shfl_xor_sync(0xffffffffu, mx1, 2));

            const float mn0 = fmaxf(m0, mx0);
            const float mn1 = fmaxf(m1, mx1);
            const float corr0 = __expf(m0 - mn0);
            const float corr1 = __expf(m1 - mn1);
            m0 = mn0; m1 = mn1;

            float s0s = 0.0f, s1s = 0.0f;
#pragma unroll
            for (int nt = 0; nt < 8; nt++) {
                accs[nt][0] = __expf(accs[nt][0] - mn0);
                accs[nt][1] = __expf(accs[nt][1] - mn0);
                accs[nt][2] = __expf(accs[nt][2] - mn1);
                accs[nt][3] = __expf(accs[nt][3] - mn1);
                s0s += accs[nt][0] + accs[nt][1];
                s1s += accs[nt][2] + accs[nt][3];
            }
            s0s += __shfl_xor_sync(0xffffffffu, s0s, 1);
            s0s += __shfl_xor_sync(0xffffffffu, s0s, 2);
            s1s += __shfl_xor_sync(0xffffffffu, s1s, 1);
            s1s += __shfl_xor_sync(0xffffffffu, s1s, 2);
            l0 = l0 * corr0 + s0s;
            l1 = l1 * corr1 + s1s;

#pragma unroll
            for (int nt = 0; nt < 16; nt++) {
                acc_o[nt][0] *= corr0; acc_o[nt][1] *= corr0;
                acc_o[nt][2] *= corr1; acc_o[nt][3] *= corr1;
            }

            // ---- O += P @ V : A-fragment via quad shuffle-transpose ----
#pragma unroll
            for (int c = 0; c < 8; c++) {
                const int src0 = (lane & ~3) | (t >> 1);
                const int src2 = src0 + 2;
                const float e00 = __shfl_sync(0xffffffffu, accs[c][0], src0);
                const float e01 = __shfl_sync(0xffffffffu, accs[c][1], src0);
                const float e10 = __shfl_sync(0xffffffffu, accs[c][2], src0);
                const float e11 = __shfl_sync(0xffffffffu, accs[c][3], src0);
                const float f00 = __shfl_sync(0xffffffffu, accs[c][0], src2);
                const float f01 = __shfl_sync(0xffffffffu, accs[c][1], src2);
                const float f10 = __shfl_sync(0xffffffffu, accs[c][2], src2);
                const float f11 = __shfl_sync(0xffffffffu, accs[c][3], src2);
                const uint32_t a0 = f2tf32((t & 1) ? e01 : e00);
                const uint32_t a1 = f2tf32((t & 1) ? e11 : e10);
                const uint32_t a2 = f2tf32((t & 1) ? f01 : f00);
                const uint32_t a3 = f2tf32((t & 1) ? f11 : f10);
#pragma unroll
                for (int nt = 0; nt < 16; nt++) {
                    uint2 bb = *(const uint2*)&Vf[((nt * 8 + c) * 32 + lane) * 2];
                    mma_tf32(acc_o[nt], a0, a1, a2, a3, bb.x, bb.y);
                }
            }
        }

        // ---- pipeline step: land ti+1, stage ti+2 ----
        CP_WAIT0();
        __syncthreads();
        if (ti + 1 < ntiles) {
            kv_convert(sm, wid, lane);
            __syncthreads();
            if (ti + 2 < ntiles)
                kv_issue(raw_addr, kp + (size_t)(ti + 2) * 64 * 128,
                         vp + (size_t)(ti + 2) * 64 * 128, tid);
        }
    }

    // ---- epilogue: normalize + write [B,T,H*D] ----
    const float inv0 = 1.0f / l0;
    const float inv1 = 1.0f / l1;
    float* o = (float*)g_attn;
    const size_t ro0 = ((size_t)(b * T_ + r0)) * C_ + h * D_;
    const size_t ro1 = ((size_t)(b * T_ + r1)) * C_ + h * D_;
#pragma unroll
    for (int nt = 0; nt < 16; nt++) {
        const int col = nt * 8 + 2 * t;
        float2 w0, w1;
        w0.x = acc_o[nt][0] * inv0; w0.y = acc_o[nt][1] * inv0;
        w1.x = acc_o[nt][2] * inv1; w1.y = acc_o[nt][3] * inv1;
        *(float2*)&o[ro0 + col] = w0;
        *(float2*)&o[ro1 + col] = w1;
    }
}

// ---------------------------------------------------------------------------
extern "C" void kernel_launch(void* const* d_in, const int* in_sizes, int n_in,
                              void* d_out, int out_size)
{
    const float* x  = (const float*)d_in[0];
    const float* wq = (const float*)d_in[1];
    const float* bq = (const float*)d_in[2];
    const float* wk = (const float*)d_in[3];
    const float* bk = (const float*)d_in[4];
    const float* wv = (const float*)d_in[5];
    const float* bv = (const float*)d_in[6];
    const float* wo = (const float*)d_in[7];

    float* out_main = (float*)d_out;                    // [B,T,C]
    float* out_k = out_main + (size_t)B_ * T_ * C_;     // [B,KV,T,D]
    float* out_v = out_k + (size_t)B_ * KV_ * T_ * D_;  // [B,KV,T,D]

    const int M = B_ * T_;  // 4096

    // Fused QKV projection
    {
        dim3 g(24, M / 128);
        qkv_gemm<<<g, 128>>>(x, wq, bq, wk, bk, wv, bv, out_k, out_v);
    }

    // RoPE on q (g_q) and k (out_k), fused single launch
    {
        const int total = PQ + PK;
        rope_all<<<(total + 255) / 256, 256>>>(out_k);
    }

    // Flash attention (tf32 MMA, cp.async pipelined, Q in registers)
    {
        cudaFuncSetAttribute(flash_mma,
                             cudaFuncAttributeMaxDynamicSharedMemorySize,
                             FL_SMEM_BYTES);
        dim3 g(T_ / 128, H_, B_);
        flash_mma<<<g, 256, FL_SMEM_BYTES>>>(out_k, out_v);
    }

    // Output projection
    {
        dim3 go(C_ / 128, M / 128);
        oproj_gemm<<<go, 128>>>(wo, out_main);
    }
}

// round 16
// speedup vs baseline: 1.8693x; 1.0136x over previous
#include <cuda_runtime.h>
#include <math.h>
#include <stdint.h>

#define B_  2
#define T_  2048
#define C_  2048
#define H_  16
#define KV_ 4
#define D_  128
#define REP_ 4
#define KDIM 2048

// Scratch (allocation-free rule: __device__ globals)
__device__ float    g_q[B_ * H_ * T_ * D_];        // [B,H,T,D] q (fp32, roped)
__device__ uint32_t g_attn[B_ * T_ * H_ * D_];     // [B,T,H*D] attn out, tf32 bits
__device__ uint32_t g_xtf[4096 * 2048];            // x pre-converted to tf32
__device__ uint32_t g_wqtf[2048 * 2048];
__device__ uint32_t g_wktf[2048 * 512];
__device__ uint32_t g_wvtf[2048 * 512];
__device__ uint32_t g_wotf[2048 * 2048];

// ---------------------------------------------------------------------------
// helpers
// ---------------------------------------------------------------------------
__device__ __forceinline__ uint32_t f2tf32(float f) {
    uint32_t u;
    asm("cvt.rna.tf32.f32 %0, %1;" : "=r"(u) : "f"(f));
    return u;
}

__device__ __forceinline__ void mma_tf32(float c[4],
                                         uint32_t a0, uint32_t a1, uint32_t a2, uint32_t a3,
                                         uint32_t b0, uint32_t b1) {
    asm volatile(
        "mma.sync.aligned.m16n8k8.row.col.f32.tf32.tf32.f32 "
        "{%0,%1,%2,%3}, {%4,%5,%6,%7}, {%8,%9}, {%0,%1,%2,%3};"
        : "+f"(c[0]), "+f"(c[1]), "+f"(c[2]), "+f"(c[3])
        : "r"(a0), "r"(a1), "r"(a2), "r"(a3), "r"(b0), "r"(b1));
}

__device__ __forceinline__ uint32_t smem_u32(const void* p) {
    uint32_t a;
    asm("{ .reg .u64 t; cvta.to.shared.u64 t, %1; cvt.u32.u64 %0, t; }" : "=r"(a) : "l"(p));
    return a;
}

__device__ __forceinline__ void cpa16(uint32_t dst, const void* src) {
    asm volatile("cp.async.cg.shared.global [%0], [%1], 16;" :: "r"(dst), "l"(src));
}
#define CP_COMMIT() asm volatile("cp.async.commit_group;" ::: "memory")
#define CP_WAIT0()  asm volatile("cp.async.wait_group 0;" ::: "memory")
#define CP_WAIT1()  asm volatile("cp.async.wait_group 1;" ::: "memory")

// ---------------------------------------------------------------------------
// Pre-convert x + weights to tf32 bits (cvt.rna — identical to old STS path)
// ---------------------------------------------------------------------------
#define N4_X  (4096 * 2048 / 4)
#define N4_WQ (2048 * 2048 / 4)
#define N4_WK (2048 * 512 / 4)
#define N4_WV (2048 * 512 / 4)
#define N4_WO (2048 * 2048 / 4)
#define N4_TOTAL (N4_X + N4_WQ + N4_WK + N4_WV + N4_WO)

__global__ void cvt_all(const float* __restrict__ x,
                        const float* __restrict__ wq, const float* __restrict__ wk,
                        const float* __restrict__ wv, const float* __restrict__ wo)
{
    size_t i = (size_t)blockIdx.x * blockDim.x + threadIdx.x;
    if (i >= N4_TOTAL) return;
    const float* src; uint32_t* dst; size_t j = i;
    if (j < N4_X)              { src = x;  dst = g_xtf; }
    else if ((j -= N4_X)  < N4_WQ) { src = wq; dst = g_wqtf; }
    else if ((j -= N4_WQ) < N4_WK) { src = wk; dst = g_wktf; }
    else if ((j -= N4_WK) < N4_WV) { src = wv; dst = g_wvtf; }
    else                       { j -= N4_WV; src = wo; dst = g_wotf; }
    float4 v = ((const float4*)src)[j];
    uint4 u;
    u.x = f2tf32(v.x); u.y = f2tf32(v.y); u.z = f2tf32(v.z); u.w = f2tf32(v.w);
    ((uint4*)dst)[j] = u;
}

// ---------------------------------------------------------------------------
// tf32 GEMM, 64x64 warp tiles, 3-stage cp.async pipeline, 1 barrier/slab.
// Inputs already tf32 bits. Fragment layout unchanged (SA=20 / SB=136).
// ---------------------------------------------------------------------------
#define SA 20
#define SB 136
#define GW_A (128 * SA)   // 2560 words per stage
#define GW_B (16 * SB)    // 2176 words per stage
#define GSTG 3
#define GEMM_SMEM_BYTES (GSTG * (GW_A + GW_B) * 4)   // 56832

__device__ __forceinline__ void gemm_issue(
    uint32_t sbase, int stage,
    const uint32_t* __restrict__ A, const uint32_t* __restrict__ W,
    int N, int m0, int n0, int k0, int tid)
{
    const uint32_t aB = sbase + stage * GW_A * 4;
    const uint32_t bB = sbase + (GSTG * GW_A + stage * GW_B) * 4;
    const int ar  = tid >> 2;
    const int akc = (tid & 3) * 4;
    const int br  = tid >> 5;
    const int bc  = (tid & 31) * 4;
#pragma unroll
    for (int c = 0; c < 4; c++) {
        cpa16(aB + ((ar + 32 * c) * SA + akc) * 4,
              A + (size_t)(m0 + ar + 32 * c) * KDIM + k0 + akc);
        cpa16(bB + ((br + 4 * c) * SB + bc) * 4,
              W + (size_t)(k0 + br + 4 * c) * N + n0 + bc);
    }
    CP_COMMIT();
}

__device__ __forceinline__ void gemm_body(
    const uint32_t* __restrict__ A, const uint32_t* __restrict__ W,
    const float* __restrict__ bias, float* __restrict__ out,
    int N, int mode, int m0, int n0, uint32_t* smem)
{
    const int tid  = threadIdx.x;          // 0..127
    const int wid  = tid >> 5;
    const int lane = tid & 31;
    const int g = lane >> 2;
    const int t = lane & 3;
    const int warp_m = (wid & 1) * 64;
    const int warp_n = (wid >> 1) * 64;
    const uint32_t sbase = smem_u32(smem);

    float acc[4][8][4];
#pragma unroll
    for (int mt = 0; mt < 4; mt++)
#pragma unroll
        for (int nt = 0; nt < 8; nt++)
#pragma unroll
            for (int i = 0; i < 4; i++) acc[mt][nt][i] = 0.0f;

    gemm_issue(sbase, 0, A, W, N, m0, n0, 0, tid);
    gemm_issue(sbase, 1, A, W, N, m0, n0, 16, tid);

    int cur = 0;
    for (int ks = 0; ks < 128; ks++) {
        if (ks <= 126) { CP_WAIT1(); } else { CP_WAIT0(); }
        __syncthreads();
        if (ks + 2 < 128) {
            int nb = cur + 2; if (nb >= GSTG) nb -= GSTG;
            gemm_issue(sbase, nb, A, W, N, m0, n0, (ks + 2) * 16, tid);
        }

        const uint32_t* As = smem + cur * GW_A;
        const uint32_t* Bs = smem + GSTG * GW_A + cur * GW_B;

#pragma unroll
        for (int kk = 0; kk < 16; kk += 8) {
            uint32_t afr[4][4];
#pragma unroll
            for (int mt = 0; mt < 4; mt++) {
                const int rb = warp_m + mt * 16;
                afr[mt][0] = As[(rb + g)     * SA + kk + t];
                afr[mt][1] = As[(rb + g + 8) * SA + kk + t];
                afr[mt][2] = As[(rb + g)     * SA + kk + t + 4];
                afr[mt][3] = As[(rb + g + 8) * SA + kk + t + 4];
            }
            uint32_t bfr[8][2];
#pragma unroll
            for (int nt = 0; nt < 8; nt++) {
                const int cn = warp_n + nt * 8 + g;
                bfr[nt][0] = Bs[(kk + t)     * SB + cn];
                bfr[nt][1] = Bs[(kk + t + 4) * SB + cn];
            }
#pragma unroll
            for (int mt = 0; mt < 4; mt++)
#pragma unroll
                for (int nt = 0; nt < 8; nt++)
                    mma_tf32(acc[mt][nt],
                             afr[mt][0], afr[mt][1], afr[mt][2], afr[mt][3],
                             bfr[nt][0], bfr[nt][1]);
        }
        cur = (cur == GSTG - 1) ? 0 : cur + 1;
    }

#pragma unroll
    for (int mt = 0; mt < 4; mt++) {
#pragma unroll
        for (int nt = 0; nt < 8; nt++) {
            const int col = n0 + warp_n + nt * 8 + 2 * t;
            float bx = 0.0f, by = 0.0f;
            if (bias) { bx = bias[col]; by = bias[col + 1]; }
#pragma unroll
            for (int half = 0; half < 2; half++) {
                const int m = m0 + warp_m + mt * 16 + g + half * 8;
                float2 r;
                r.x = acc[mt][nt][half * 2 + 0] + bx;
                r.y = acc[mt][nt][half * 2 + 1] + by;
                if (mode == 0) {
                    *(float2*)&out[(size_t)m * N + col] = r;
                } else {
                    const int b  = m >> 11;
                    const int tt = m & (T_ - 1);
                    const int h  = col >> 7;
                    const int dd = col & 127;
                    *(float2*)&out[((size_t)(b * (N >> 7) + h) * T_ + tt) * D_ + dd] = r;
                }
            }
        }
    }
}

__global__ __launch_bounds__(128, 2) void qkv_gemm(
    const float* __restrict__ bq, const float* __restrict__ bk,
    const float* __restrict__ bv,
    float* __restrict__ out_k, float* __restrict__ out_v)
{
    extern __shared__ uint32_t gsm[];
    const int bx = blockIdx.x;
    const uint32_t* W; const float* bias; float* out; int N; int n0;
    if (bx < 16)      { W = g_wqtf; bias = bq; out = (float*)g_q; N = 2048; n0 = bx * 128; }
    else if (bx < 20) { W = g_wktf; bias = bk; out = out_k; N = 512; n0 = (bx - 16) * 128; }
    else              { W = g_wvtf; bias = bv; out = out_v; N = 512; n0 = (bx - 20) * 128; }
    gemm_body(g_xtf, W, bias, out, N, 1, blockIdx.y * 128, n0, gsm);
}

__global__ __launch_bounds__(128, 2) void oproj_gemm(float* __restrict__ out)
{
    extern __shared__ uint32_t gsm[];
    gemm_body(g_attn, g_wotf, nullptr, out, 2048, 0,
              blockIdx.y * 128, blockIdx.x * 128, gsm);
}

// ---------------------------------------------------------------------------
// RoPE in place, fused q (g_q) + k (out_k): pair (j, j+64)
// ---------------------------------------------------------------------------
#define PQ (B_ * H_ * T_ * 64)
#define PK (B_ * KV_ * T_ * 64)

__global__ void rope_all(float* __restrict__ out_k)
{
    int idx = blockIdx.x * blockDim.x + threadIdx.x;
    float* x;
    if (idx < PQ) { x = (float*)g_q; }
    else          { x = out_k; idx -= PQ; if (idx >= PK) return; }

    const int j = idx & 63;
    const int t = (idx >> 6) & (T_ - 1);
    const int bh = idx >> 17;

    const float freq = expf(-13.815510557964274f * ((float)j / 64.0f));
    const float theta = (float)t * freq;
    const float s = sinf(theta);
    const float c = cosf(theta);

    float* base = x + ((size_t)bh * T_ + t) * D_;
    const float v1 = base[j];
    const float v2 = base[j + 64];
    base[j]      = c * v1 - s * v2;
    base[j + 64] = c * v2 + s * v1;
}

// ---------------------------------------------------------------------------
// Flash attention, tf32 MMA, cp.async-pipelined K/V, Q in registers (r15).
// Epilogue now writes g_attn in tf32 bits (same cvt.rna oproj used before).
// ---------------------------------------------------------------------------
#define KF_W  0
#define VF_W  8192
#define RAW_W 16384
#define FL_SMEM_BYTES (32768 * 4)

__device__ __forceinline__ void kv_issue(uint32_t raw_addr,
                                         const float* ks, const float* vs, int tid)
{
#pragma unroll
    for (int i = 0; i < 8; i++) {
        const int off = (i * 256 + tid) * 4;
        cpa16(raw_addr + off * 4, ks + off);
        cpa16(raw_addr + 32768 + off * 4, vs + off);
    }
    CP_COMMIT();
}

__device__ __forceinline__ void kv_convert(uint32_t* sm, int wid, int lane)
{
    const float* rk = (const float*)(sm + RAW_W);
    const float* rv = (const float*)(sm + RAW_W + 8192);
    uint32_t* Kf = sm + KF_W;
    uint32_t* Vf = sm + VF_W;
#pragma unroll
    for (int j = 0; j < 8; j++) {
        const int r = wid * 8 + j;
        const int ntk = r >> 3, gk = r & 7;
        const int csV = r >> 3, tsV = j & 3, hsV = j >> 2;
#pragma unroll
        for (int c = 0; c < 4; c++) {
            const int dd = lane + 32 * c;
            const int ck = dd >> 3, uk = dd & 7;
            Kf[((ntk * 16 + ck) * 32 + gk * 4 + (uk & 3)) * 2 + (uk >> 2)] =
                f2tf32(rk[r * 128 + dd]);
            const int ntv = dd >> 3, gv = dd & 7;
            Vf[((ntv * 8 + csV) * 32 + gv * 4 + tsV) * 2 + hsV] =
                f2tf32(rv[r * 128 + dd]);
        }
    }
}

__global__ __launch_bounds__(256, 1) void flash_mma(
    const float* __restrict__ k, const float* __restrict__ v)
{
    extern __shared__ uint32_t sm[];
    uint32_t* Kf = sm + KF_W;
    uint32_t* Vf = sm + VF_W;

    const int tid = threadIdx.x;
    const int lane = tid & 31;
    const int wid = tid >> 5;
    const int g = lane >> 2;
    const int t = lane & 3;

    const int q0 = (int)(gridDim.x - 1 - blockIdx.x) * 128;
    const int h  = blockIdx.y;
    const int b  = blockIdx.z;
    const int kvh = h >> 2;

    const float* qp = (const float*)g_q + ((size_t)(b * H_ + h) * T_ + q0) * D_;
    const float* kp = k + ((size_t)(b * KV_ + kvh) * T_) * D_;
    const float* vp = v + ((size_t)(b * KV_ + kvh) * T_) * D_;

    const uint32_t sbase = smem_u32(sm);
    const uint32_t raw_addr = sbase + RAW_W * 4;

    // stage Q tile via cp.async
#pragma unroll
    for (int i = 0; i < 16; i++) {
        const int off = (i * 256 + tid) * 4;
        cpa16(raw_addr + off * 4, qp + off);
    }
    CP_COMMIT();
    CP_WAIT0();
    __syncthreads();

    uint32_t qa[16][4];
    {
        const float* qstage = (const float*)(sm + RAW_W);
        const int R0 = wid * 16 + g, R1 = R0 + 8;
#pragma unroll
        for (int c = 0; c < 16; c++) {
            qa[c][0] = f2tf32(qstage[R0 * 128 + c * 8 + t]);
            qa[c][1] = f2tf32(qstage[R1 * 128 + c * 8 + t]);
            qa[c][2] = f2tf32(qstage[R0 * 128 + c * 8 + t + 4]);
            qa[c][3] = f2tf32(qstage[R1 * 128 + c * 8 + t + 4]);
        }
    }
    __syncthreads();

    float acc_o[16][4];
#pragma unroll
    for (int nt = 0; nt < 16; nt++)
#pragma unroll
        for (int i = 0; i < 4; i++) acc_o[nt][i] = 0.0f;

    float m0 = -INFINITY, m1 = -INFINITY, l0 = 0.0f, l1 = 0.0f;
    const float scale = 0.08838834764831845f;

    const int r0 = q0 + wid * 16 + g;
    const int r1 = r0 + 8;
    const int warp_last = q0 + wid * 16 + 15;
    const int ntiles = q0 / 64 + 2;

    kv_issue(raw_addr, kp, vp, tid);
    CP_WAIT0();
    __syncthreads();
    kv_convert(sm, wid, lane);
    __syncthreads();
    if (ntiles > 1) kv_issue(raw_addr, kp + 64 * 128, vp + 64 * 128, tid);

    for (int ti = 0; ti < ntiles; ti++) {
        const int s0 = ti * 64;

        if (s0 <= warp_last) {
            float accs[8][4];
#pragma unroll
            for (int nt = 0; nt < 8; nt++)
#pragma unroll
                for (int i = 0; i < 4; i++) accs[nt][i] = 0.0f;

#pragma unroll
            for (int c = 0; c < 16; c++) {
#pragma unroll
                for (int nt = 0; nt < 8; nt++) {
                    uint2 bb = *(const uint2*)&Kf[((nt * 16 + c) * 32 + lane) * 2];
                    mma_tf32(accs[nt], qa[c][0], qa[c][1], qa[c][2], qa[c][3],
                             bb.x, bb.y);
                }
            }

            float mx0 = -INFINITY, mx1 = -INFINITY;
#pragma unroll
            for (int nt = 0; nt < 8; nt++) {
                const int c0 = s0 + nt * 8 + 2 * t;
                accs[nt][0] = (c0     <= r0) ? accs[nt][0] * scale : -INFINITY;
                accs[nt][1] = (c0 + 1 <= r0) ? accs[nt][1] * scale : -INFINITY;
                accs[nt][2] = (c0     <= r1) ? accs[nt][2] * scale : -INFINITY;
                accs[nt][3] = (c0 + 1 <= r1) ? accs[nt][3] * scale : -INFINITY;
                mx0 = fmaxf(mx0, fmaxf(accs[nt][0], accs[nt][1]));
                mx1 = fmaxf(mx1, fmaxf(accs[nt][2], accs[nt][3]));
            }
            mx0 = fmaxf(mx0, __shfl_xor_sync(0xffffffffu, mx0, 1));
            mx0 = fmaxf(mx0, __shfl_xor_sync(0xffffffffu, mx0, 2));
            mx1 = fmaxf(mx1, __shfl_xor_sync(0xffffffffu, mx1, 1));
            mx1 = fmaxf(mx1, __shfl_xor_sync(0xffffffffu, mx1, 2));

            const float mn0 = fmaxf(m0, mx0);
            const float mn1 = fmaxf(m1, mx1);
            const float corr0 = __expf(m0 - mn0);
            const float corr1 = __expf(m1 - mn1);
            m0 = mn0; m1 = mn1;

            float s0s = 0.0f, s1s = 0.0f;
#pragma unroll
            for (int nt = 0; nt < 8; nt++) {
                accs[nt][0] = __expf(accs[nt][0] - mn0);
                accs[nt][1] = __expf(accs[nt][1] - mn0);
                accs[nt][2] = __expf(accs[nt][2] - mn1);
                accs[nt][3] = __expf(accs[nt][3] - mn1);
                s0s += accs[nt][0] + accs[nt][1];
                s1s += accs[nt][2] + accs[nt][3];
            }
            s0s += __shfl_xor_sync(0xffffffffu, s0s, 1);
            s0s += __shfl_xor_sync(0xffffffffu, s0s, 2);
            s1s += __shfl_xor_sync(0xffffffffu, s1s, 1);
            s1s += __shfl_xor_sync(0xffffffffu, s1s, 2);
            l0 = l0 * corr0 + s0s;
            l1 = l1 * corr1 + s1s;

#pragma unroll
            for (int nt = 0; nt < 16; nt++) {
                acc_o[nt][0] *= corr0; acc_o[nt][1] *= corr0;
                acc_o[nt][2] *= corr1; acc_o[nt][3] *= corr1;
            }

#pragma unroll
            for (int c = 0; c < 8; c++) {
                const int src0 = (lane & ~3) | (t >> 1);
                const int src2 = src0 + 2;
                const float e00 = __shfl_sync(0xffffffffu, accs[c][0], src0);
                const float e01 = __shfl_sync(0xffffffffu, accs[c][1], src0);
                const float e10 = __shfl_sync(0xffffffffu, accs[c][2], src0);
                const float e11 = __shfl_sync(0xffffffffu, accs[c][3], src0);
                const float f00 = __shfl_sync(0xffffffffu, accs[c][0], src2);
                const float f01 = __shfl_sync(0xffffffffu, accs[c][1], src2);
                const float f10 = __shfl_sync(0xffffffffu, accs[c][2], src2);
                const float f11 = __shfl_sync(0xffffffffu, accs[c][3], src2);
                const uint32_t a0 = f2tf32((t & 1) ? e01 : e00);
                const uint32_t a1 = f2tf32((t & 1) ? e11 : e10);
                const uint32_t a2 = f2tf32((t & 1) ? f01 : f00);
                const uint32_t a3 = f2tf32((t & 1) ? f11 : f10);
#pragma unroll
                for (int nt = 0; nt < 16; nt++) {
                    uint2 bb = *(const uint2*)&Vf[((nt * 8 + c) * 32 + lane) * 2];
                    mma_tf32(acc_o[nt], a0, a1, a2, a3, bb.x, bb.y);
                }
            }
        }

        CP_WAIT0();
        __syncthreads();
        if (ti + 1 < ntiles) {
            kv_convert(sm, wid, lane);
            __syncthreads();
            if (ti + 2 < ntiles)
                kv_issue(raw_addr, kp + (size_t)(ti + 2) * 64 * 128,
                         vp + (size_t)(ti + 2) * 64 * 128, tid);
        }
    }

    // epilogue: normalize + write g_attn as tf32 bits
    const float inv0 = 1.0f / l0;
    const float inv1 = 1.0f / l1;
    uint32_t* o = g_attn;
    const size_t ro0 = ((size_t)(b * T_ + r0)) * C_ + h * D_;
    const size_t ro1 = ((size_t)(b * T_ + r1)) * C_ + h * D_;
#pragma unroll
    for (int nt = 0; nt < 16; nt++) {
        const int col = nt * 8 + 2 * t;
        uint2 w0, w1;
        w0.x = f2tf32(acc_o[nt][0] * inv0); w0.y = f2tf32(acc_o[nt][1] * inv0);
        w1.x = f2tf32(acc_o[nt][2] * inv1); w1.y = f2tf32(acc_o[nt][3] * inv1);
        *(uint2*)&o[ro0 + col] = w0;
        *(uint2*)&o[ro1 + col] = w1;
    }
}

// ---------------------------------------------------------------------------
extern "C" void kernel_launch(void* const* d_in, const int* in_sizes, int n_in,
                              void* d_out, int out_size)
{
    const float* x  = (const float*)d_in[0];
    const float* wq = (const float*)d_in[1];
    const float* bq = (const float*)d_in[2];
    const float* wk = (const float*)d_in[3];
    const float* bk = (const float*)d_in[4];
    const float* wv = (const float*)d_in[5];
    const float* bv = (const float*)d_in[6];
    const float* wo = (const float*)d_in[7];

    float* out_main = (float*)d_out;                    // [B,T,C]
    float* out_k = out_main + (size_t)B_ * T_ * C_;     // [B,KV,T,D]
    float* out_v = out_k + (size_t)B_ * KV_ * T_ * D_;  // [B,KV,T,D]

    const int M = B_ * T_;  // 4096

    cudaFuncSetAttribute(qkv_gemm,
                         cudaFuncAttributeMaxDynamicSharedMemorySize, GEMM_SMEM_BYTES);
    cudaFuncSetAttribute(oproj_gemm,
                         cudaFuncAttributeMaxDynamicSharedMemorySize, GEMM_SMEM_BYTES);
    cudaFuncSetAttribute(flash_mma,
                         cudaFuncAttributeMaxDynamicSharedMemorySize, FL_SMEM_BYTES);

    // Pre-convert x + weights to tf32 bits
    {
        const int blocks = (N4_TOTAL + 255) / 256;
        cvt_all<<<blocks, 256>>>(x, wq, wk, wv, wo);
    }

    // Fused QKV projection (cp.async pipelined)
    {
        dim3 g(24, M / 128);
        qkv_gemm<<<g, 128, GEMM_SMEM_BYTES>>>(bq, bk, bv, out_k, out_v);
    }

    // RoPE on q (g_q) and k (out_k)
    {
        const int total = PQ + PK;
        rope_all<<<(total + 255) / 256, 256>>>(out_k);
    }

    // Flash attention (tf32 MMA, cp.async pipelined, Q in registers)
    {
        dim3 g(T_ / 128, H_, B_);
        flash_mma<<<g, 256, FL_SMEM_BYTES>>>(out_k, out_v);
    }

    // Output projection (A = g_attn tf32)
    {
        dim3 go(C_ / 128, M / 128);
        oproj_gemm<<<go, 128, GEMM_SMEM_BYTES>>>(out_main);
    }
}

// round 17
// speedup vs baseline: 1.8942x; 1.0134x over previous
#include <cuda_runtime.h>
#include <math.h>
#include <stdint.h>

#define B_  2
#define T_  2048
#define C_  2048
#define H_  16
#define KV_ 4
#define D_  128
#define REP_ 4
#define KDIM 2048

// Scratch (allocation-free rule: __device__ globals)
__device__ float    g_q[B_ * H_ * T_ * D_];        // [B,H,T,D] q (fp32, roped)
__device__ uint32_t g_attn[B_ * T_ * H_ * D_];     // [B,T,H*D] attn out, tf32 bits
__device__ uint32_t g_xtf[4096 * 2048];            // x pre-converted to tf32
__device__ uint32_t g_wqtf[2048 * 2048];
__device__ uint32_t g_wktf[2048 * 512];
__device__ uint32_t g_wvtf[2048 * 512];
__device__ uint32_t g_wotf[2048 * 2048];

// ---------------------------------------------------------------------------
// helpers
// ---------------------------------------------------------------------------
__device__ __forceinline__ uint32_t f2tf32(float f) {
    uint32_t u;
    asm("cvt.rna.tf32.f32 %0, %1;" : "=r"(u) : "f"(f));
    return u;
}

__device__ __forceinline__ void mma_tf32(float c[4],
                                         uint32_t a0, uint32_t a1, uint32_t a2, uint32_t a3,
                                         uint32_t b0, uint32_t b1) {
    asm volatile(
        "mma.sync.aligned.m16n8k8.row.col.f32.tf32.tf32.f32 "
        "{%0,%1,%2,%3}, {%4,%5,%6,%7}, {%8,%9}, {%0,%1,%2,%3};"
        : "+f"(c[0]), "+f"(c[1]), "+f"(c[2]), "+f"(c[3])
        : "r"(a0), "r"(a1), "r"(a2), "r"(a3), "r"(b0), "r"(b1));
}

__device__ __forceinline__ uint32_t smem_u32(const void* p) {
    uint32_t a;
    asm("{ .reg .u64 t; cvta.to.shared.u64 t, %1; cvt.u32.u64 %0, t; }" : "=r"(a) : "l"(p));
    return a;
}

__device__ __forceinline__ void cpa16(uint32_t dst, const void* src) {
    asm volatile("cp.async.cg.shared.global [%0], [%1], 16;" :: "r"(dst), "l"(src));
}
#define CP_COMMIT() asm volatile("cp.async.commit_group;" ::: "memory")
#define CP_WAIT0()  asm volatile("cp.async.wait_group 0;" ::: "memory")
#define CP_WAIT1()  asm volatile("cp.async.wait_group 1;" ::: "memory")

// ---------------------------------------------------------------------------
// Pre-convert x + weights to tf32 bits (cvt.rna — identical numerics)
// ---------------------------------------------------------------------------
#define N4_X  (4096 * 2048 / 4)
#define N4_WQ (2048 * 2048 / 4)
#define N4_WK (2048 * 512 / 4)
#define N4_WV (2048 * 512 / 4)
#define N4_WO (2048 * 2048 / 4)
#define N4_TOTAL (N4_X + N4_WQ + N4_WK + N4_WV + N4_WO)

__global__ void cvt_all(const float* __restrict__ x,
                        const float* __restrict__ wq, const float* __restrict__ wk,
                        const float* __restrict__ wv, const float* __restrict__ wo)
{
    size_t i = (size_t)blockIdx.x * blockDim.x + threadIdx.x;
    if (i >= N4_TOTAL) return;
    const float* src; uint32_t* dst; size_t j = i;
    if (j < N4_X)              { src = x;  dst = g_xtf; }
    else if ((j -= N4_X)  < N4_WQ) { src = wq; dst = g_wqtf; }
    else if ((j -= N4_WQ) < N4_WK) { src = wk; dst = g_wktf; }
    else if ((j -= N4_WK) < N4_WV) { src = wv; dst = g_wvtf; }
    else                       { j -= N4_WV; src = wo; dst = g_wotf; }
    float4 v = ((const float4*)src)[j];
    uint4 u;
    u.x = f2tf32(v.x); u.y = f2tf32(v.y); u.z = f2tf32(v.z); u.w = f2tf32(v.w);
    ((uint4*)dst)[j] = u;
}

// ---------------------------------------------------------------------------
// tf32 GEMM (r16): 64x64 warp tiles, 3-stage cp.async pipeline.
// ---------------------------------------------------------------------------
#define SA 20
#define SB 136
#define GW_A (128 * SA)
#define GW_B (16 * SB)
#define GSTG 3
#define GEMM_SMEM_BYTES (GSTG * (GW_A + GW_B) * 4)

__device__ __forceinline__ void gemm_issue(
    uint32_t sbase, int stage,
    const uint32_t* __restrict__ A, const uint32_t* __restrict__ W,
    int N, int m0, int n0, int k0, int tid)
{
    const uint32_t aB = sbase + stage * GW_A * 4;
    const uint32_t bB = sbase + (GSTG * GW_A + stage * GW_B) * 4;
    const int ar  = tid >> 2;
    const int akc = (tid & 3) * 4;
    const int br  = tid >> 5;
    const int bc  = (tid & 31) * 4;
#pragma unroll
    for (int c = 0; c < 4; c++) {
        cpa16(aB + ((ar + 32 * c) * SA + akc) * 4,
              A + (size_t)(m0 + ar + 32 * c) * KDIM + k0 + akc);
        cpa16(bB + ((br + 4 * c) * SB + bc) * 4,
              W + (size_t)(k0 + br + 4 * c) * N + n0 + bc);
    }
    CP_COMMIT();
}

__device__ __forceinline__ void gemm_body(
    const uint32_t* __restrict__ A, const uint32_t* __restrict__ W,
    const float* __restrict__ bias, float* __restrict__ out,
    int N, int mode, int m0, int n0, uint32_t* smem)
{
    const int tid  = threadIdx.x;
    const int wid  = tid >> 5;
    const int lane = tid & 31;
    const int g = lane >> 2;
    const int t = lane & 3;
    const int warp_m = (wid & 1) * 64;
    const int warp_n = (wid >> 1) * 64;
    const uint32_t sbase = smem_u32(smem);

    float acc[4][8][4];
#pragma unroll
    for (int mt = 0; mt < 4; mt++)
#pragma unroll
        for (int nt = 0; nt < 8; nt++)
#pragma unroll
            for (int i = 0; i < 4; i++) acc[mt][nt][i] = 0.0f;

    gemm_issue(sbase, 0, A, W, N, m0, n0, 0, tid);
    gemm_issue(sbase, 1, A, W, N, m0, n0, 16, tid);

    int cur = 0;
    for (int ks = 0; ks < 128; ks++) {
        if (ks <= 126) { CP_WAIT1(); } else { CP_WAIT0(); }
        __syncthreads();
        if (ks + 2 < 128) {
            int nb = cur + 2; if (nb >= GSTG) nb -= GSTG;
            gemm_issue(sbase, nb, A, W, N, m0, n0, (ks + 2) * 16, tid);
        }

        const uint32_t* As = smem + cur * GW_A;
        const uint32_t* Bs = smem + GSTG * GW_A + cur * GW_B;

#pragma unroll
        for (int kk = 0; kk < 16; kk += 8) {
            uint32_t afr[4][4];
#pragma unroll
            for (int mt = 0; mt < 4; mt++) {
                const int rb = warp_m + mt * 16;
                afr[mt][0] = As[(rb + g)     * SA + kk + t];
                afr[mt][1] = As[(rb + g + 8) * SA + kk + t];
                afr[mt][2] = As[(rb + g)     * SA + kk + t + 4];
                afr[mt][3] = As[(rb + g + 8) * SA + kk + t + 4];
            }
            uint32_t bfr[8][2];
#pragma unroll
            for (int nt = 0; nt < 8; nt++) {
                const int cn = warp_n + nt * 8 + g;
                bfr[nt][0] = Bs[(kk + t)     * SB + cn];
                bfr[nt][1] = Bs[(kk + t + 4) * SB + cn];
            }
#pragma unroll
            for (int mt = 0; mt < 4; mt++)
#pragma unroll
                for (int nt = 0; nt < 8; nt++)
                    mma_tf32(acc[mt][nt],
                             afr[mt][0], afr[mt][1], afr[mt][2], afr[mt][3],
                             bfr[nt][0], bfr[nt][1]);
        }
        cur = (cur == GSTG - 1) ? 0 : cur + 1;
    }

#pragma unroll
    for (int mt = 0; mt < 4; mt++) {
#pragma unroll
        for (int nt = 0; nt < 8; nt++) {
            const int col = n0 + warp_n + nt * 8 + 2 * t;
            float bx = 0.0f, by = 0.0f;
            if (bias) { bx = bias[col]; by = bias[col + 1]; }
#pragma unroll
            for (int half = 0; half < 2; half++) {
                const int m = m0 + warp_m + mt * 16 + g + half * 8;
                float2 r;
                r.x = acc[mt][nt][half * 2 + 0] + bx;
                r.y = acc[mt][nt][half * 2 + 1] + by;
                if (mode == 0) {
                    *(float2*)&out[(size_t)m * N + col] = r;
                } else {
                    const int b  = m >> 11;
                    const int tt = m & (T_ - 1);
                    const int h  = col >> 7;
                    const int dd = col & 127;
                    *(float2*)&out[((size_t)(b * (N >> 7) + h) * T_ + tt) * D_ + dd] = r;
                }
            }
        }
    }
}

__global__ __launch_bounds__(128, 2) void qkv_gemm(
    const float* __restrict__ bq, const float* __restrict__ bk,
    const float* __restrict__ bv,
    float* __restrict__ out_k, float* __restrict__ out_v)
{
    extern __shared__ uint32_t gsm[];
    const int bx = blockIdx.x;
    const uint32_t* W; const float* bias; float* out; int N; int n0;
    if (bx < 16)      { W = g_wqtf; bias = bq; out = (float*)g_q; N = 2048; n0 = bx * 128; }
    else if (bx < 20) { W = g_wktf; bias = bk; out = out_k; N = 512; n0 = (bx - 16) * 128; }
    else              { W = g_wvtf; bias = bv; out = out_v; N = 512; n0 = (bx - 20) * 128; }
    gemm_body(g_xtf, W, bias, out, N, 1, blockIdx.y * 128, n0, gsm);
}

__global__ __launch_bounds__(128, 2) void oproj_gemm(float* __restrict__ out)
{
    extern __shared__ uint32_t gsm[];
    gemm_body(g_attn, g_wotf, nullptr, out, 2048, 0,
              blockIdx.y * 128, blockIdx.x * 128, gsm);
}

// ---------------------------------------------------------------------------
// RoPE in place, fused q (g_q) + k (out_k)
// ---------------------------------------------------------------------------
#define PQ (B_ * H_ * T_ * 64)
#define PK (B_ * KV_ * T_ * 64)

__global__ void rope_all(float* __restrict__ out_k)
{
    int idx = blockIdx.x * blockDim.x + threadIdx.x;
    float* x;
    if (idx < PQ) { x = (float*)g_q; }
    else          { x = out_k; idx -= PQ; if (idx >= PK) return; }

    const int j = idx & 63;
    const int t = (idx >> 6) & (T_ - 1);
    const int bh = idx >> 17;

    const float freq = expf(-13.815510557964274f * ((float)j / 64.0f));
    const float theta = (float)t * freq;
    const float s = sinf(theta);
    const float c = cosf(theta);

    float* base = x + ((size_t)bh * T_ + t) * D_;
    const float v1 = base[j];
    const float v2 = base[j + 64];
    base[j]      = c * v1 - s * v2;
    base[j + 64] = c * v2 + s * v1;
}

// ---------------------------------------------------------------------------
// Flash attention, tf32 MMA, cp.async K/V with XOR-swizzled staging,
// LDS.128-paired fragment buffers, vectorized convert.
// 256 threads, Q tile 128 rows, KV tile 64 rows.
// Kf uint4 @ (nt*8+cp)*32+lane : {b0(c=2cp), b1(2cp), b0(2cp+1), b1(2cp+1)}
// Vf uint4 @ (c*8+ntp)*32+lane : {b0(nt=2ntp), b1(2ntp), b0(2ntp+1), b1(2ntp+1)}
// Raw K/Q swizzle: chunk cb -> cb ^ (r & 31). Raw V: cb -> cb ^ ((r & 3) << 1).
// ---------------------------------------------------------------------------
#define KF_W  0
#define VF_W  8192
#define RAW_W 16384
#define FL_SMEM_BYTES (32768 * 4)

__device__ __forceinline__ void kv_issue(uint32_t raw_addr,
                                         const float* ks, const float* vs, int tid)
{
#pragma unroll
    for (int i = 0; i < 8; i++) {
        const int ci = i * 256 + tid;      // 16B chunk index 0..2047
        const int r  = ci >> 5;            // row 0..63
        const int cb = ci & 31;            // 16B block in row
        const int wk = r * 128 + ((cb ^ (r & 31)) << 2);
        const int wv = r * 128 + ((cb ^ ((r & 3) << 1)) << 2);
        const float* src = ks + r * 128 + cb * 4;
        const float* srcv = vs + r * 128 + cb * 4;
        cpa16(raw_addr + wk * 4, src);
        cpa16(raw_addr + 32768 + wv * 4, srcv);
    }
    CP_COMMIT();
}

__device__ __forceinline__ void kv_convert(uint32_t* sm, int wid, int lane)
{
    const int g = lane >> 2, t = lane & 3;
    const float* rawk = (const float*)(sm + RAW_W);
    const float* rawv = rawk + 8192;
    uint32_t* Kf = sm + KF_W;
    uint32_t* Vf = sm + VF_W;

    // K: this warp handles nt = wid; rows nt*8+g
    const int rowK = wid * 8 + g;
    const int sK = rowK & 31;
    const float* rkb = rawk + rowK * 128;
#pragma unroll
    for (int cp = 0; cp < 8; cp++) {
        const int c0 = 16 * cp + t;
        uint4 w;
        w.x = f2tf32(rkb[((((c0     ) >> 2) ^ sK) << 2) + t]);
        w.y = f2tf32(rkb[((((c0 + 4 ) >> 2) ^ sK) << 2) + t]);
        w.z = f2tf32(rkb[((((c0 + 8 ) >> 2) ^ sK) << 2) + t]);
        w.w = f2tf32(rkb[((((c0 + 12) >> 2) ^ sK) << 2) + t]);
        *(uint4*)&Kf[((wid * 8 + cp) * 32 + lane) * 4] = w;
    }

    // V: this warp handles c = wid; rows c*8+t and c*8+t+4
    const int rv0 = wid * 8 + t;
    const int rv1 = rv0 + 4;
    const int sv = t << 1;                 // (row & 3) << 1, same for both rows
    const float* rv0b = rawv + rv0 * 128;
    const float* rv1b = rawv + rv1 * 128;
#pragma unroll
    for (int ntp = 0; ntp < 8; ntp++) {
        const int col0 = 16 * ntp + g;
        const int col1 = col0 + 8;
        uint4 w;
        w.x = f2tf32(rv0b[((((col0) >> 2) ^ sv) << 2) + (col0 & 3)]);
        w.y = f2tf32(rv1b[((((col0) >> 2) ^ sv) << 2) + (col0 & 3)]);
        w.z = f2tf32(rv0b[((((col1) >> 2) ^ sv) << 2) + (col1 & 3)]);
        w.w = f2tf32(rv1b[((((col1) >> 2) ^ sv) << 2) + (col1 & 3)]);
        *(uint4*)&Vf[((wid * 8 + ntp) * 32 + lane) * 4] = w;
    }
}

__global__ __launch_bounds__(256, 1) void flash_mma(
    const float* __restrict__ k, const float* __restrict__ v)
{
    extern __shared__ uint32_t sm[];
    uint32_t* Kf = sm + KF_W;
    uint32_t* Vf = sm + VF_W;

    const int tid = threadIdx.x;
    const int lane = tid & 31;
    const int wid = tid >> 5;
    const int g = lane >> 2;
    const int t = lane & 3;

    const int q0 = (int)(gridDim.x - 1 - blockIdx.x) * 128;
    const int h  = blockIdx.y;
    const int b  = blockIdx.z;
    const int kvh = h >> 2;

    const float* qp = (const float*)g_q + ((size_t)(b * H_ + h) * T_ + q0) * D_;
    const float* kp = k + ((size_t)(b * KV_ + kvh) * T_) * D_;
    const float* vp = v + ((size_t)(b * KV_ + kvh) * T_) * D_;

    const uint32_t sbase = smem_u32(sm);
    const uint32_t raw_addr = sbase + RAW_W * 4;

    // ---- stage Q tile via cp.async with K-style swizzle ----
#pragma unroll
    for (int i = 0; i < 16; i++) {
        const int ci = i * 256 + tid;      // chunk 0..4095
        const int r  = ci >> 5;            // row 0..127
        const int cb = ci & 31;
        const int wq = r * 128 + ((cb ^ (r & 31)) << 2);
        cpa16(raw_addr + wq * 4, qp + r * 128 + cb * 4);
    }
    CP_COMMIT();
    CP_WAIT0();
    __syncthreads();

    // ---- Q fragments into registers (swizzled, conflict-free) ----
    uint32_t qa[16][4];
    {
        const float* qstage = (const float*)(sm + RAW_W);
        const int R0 = wid * 16 + g, R1 = R0 + 8;
        const int s0q = R0 & 31, s1q = R1 & 31;
#pragma unroll
        for (int c = 0; c < 16; c++) {
            qa[c][0] = f2tf32(qstage[R0 * 128 + (((2 * c    ) ^ s0q) << 2) + t]);
            qa[c][1] = f2tf32(qstage[R1 * 128 + (((2 * c    ) ^ s1q) << 2) + t]);
            qa[c][2] = f2tf32(qstage[R0 * 128 + (((2 * c + 1) ^ s0q) << 2) + t]);
            qa[c][3] = f2tf32(qstage[R1 * 128 + (((2 * c + 1) ^ s1q) << 2) + t]);
        }
    }
    __syncthreads();

    float acc_o[16][4];
#pragma unroll
    for (int nt = 0; nt < 16; nt++)
#pragma unroll
        for (int i = 0; i < 4; i++) acc_o[nt][i] = 0.0f;

    float m0 = -INFINITY, m1 = -INFINITY, l0 = 0.0f, l1 = 0.0f;
    const float scale = 0.08838834764831845f;

    const int r0 = q0 + wid * 16 + g;
    const int r1 = r0 + 8;
    const int warp_last = q0 + wid * 16 + 15;
    const int ntiles = q0 / 64 + 2;

    kv_issue(raw_addr, kp, vp, tid);
    CP_WAIT0();
    __syncthreads();
    kv_convert(sm, wid & 7, lane);
    __syncthreads();
    if (ntiles > 1) kv_issue(raw_addr, kp + 64 * 128, vp + 64 * 128, tid);

    for (int ti = 0; ti < ntiles; ti++) {
        const int s0 = ti * 64;

        if (s0 <= warp_last) {
            // ---- S = Q @ K^T (paired LDS.128 B-frags) ----
            float accs[8][4];
#pragma unroll
            for (int nt = 0; nt < 8; nt++)
#pragma unroll
                for (int i = 0; i < 4; i++) accs[nt][i] = 0.0f;

#pragma unroll
            for (int cp = 0; cp < 8; cp++) {
#pragma unroll
                for (int nt = 0; nt < 8; nt++) {
                    uint4 bb = *(const uint4*)&Kf[((nt * 8 + cp) * 32 + lane) * 4];
                    mma_tf32(accs[nt], qa[2 * cp][0], qa[2 * cp][1],
                             qa[2 * cp][2], qa[2 * cp][3], bb.x, bb.y);
                    mma_tf32(accs[nt], qa[2 * cp + 1][0], qa[2 * cp + 1][1],
                             qa[2 * cp + 1][2], qa[2 * cp + 1][3], bb.z, bb.w);
                }
            }

            // ---- online softmax ----
            float mx0 = -INFINITY, mx1 = -INFINITY;
#pragma unroll
            for (int nt = 0; nt < 8; nt++) {
                const int c0 = s0 + nt * 8 + 2 * t;
                accs[nt][0] = (c0     <= r0) ? accs[nt][0] * scale : -INFINITY;
                accs[nt][1] = (c0 + 1 <= r0) ? accs[nt][1] * scale : -INFINITY;
                accs[nt][2] = (c0     <= r1) ? accs[nt][2] * scale : -INFINITY;
                accs[nt][3] = (c0 + 1 <= r1) ? accs[nt][3] * scale : -INFINITY;
                mx0 = fmaxf(mx0, fmaxf(accs[nt][0], accs[nt][1]));
                mx1 = fmaxf(mx1, fmaxf(accs[nt][2], accs[nt][3]));
            }
            mx0 = fmaxf(mx0, __shfl_xor_sync(0xffffffffu, mx0, 1));
            mx0 = fmaxf(mx0, __shfl_xor_sync(0xffffffffu, mx0, 2));
            mx1 = fmaxf(mx1, __shfl_xor_sync(0xffffffffu, mx1, 1));
            mx1 = fmaxf(mx1, __shfl_xor_sync(0xffffffffu, mx1, 2));

            const float mn0 = fmaxf(m0, mx0);
            const float mn1 = fmaxf(m1, mx1);
            const float corr0 = __expf(m0 - mn0);
            const float corr1 = __expf(m1 - mn1);
            m0 = mn0; m1 = mn1;

            float s0s = 0.0f, s1s = 0.0f;
#pragma unroll
            for (int nt = 0; nt < 8; nt++) {
                accs[nt][0] = __expf(accs[nt][0] - mn0);
                accs[nt][1] = __expf(accs[nt][1] - mn0);
                accs[nt][2] = __expf(accs[nt][2] - mn1);
                accs[nt][3] = __expf(accs[nt][3] - mn1);
                s0s += accs[nt][0] + accs[nt][1];
                s1s += accs[nt][2] + accs[nt][3];
            }
            s0s += __shfl_xor_sync(0xffffffffu, s0s, 1);
            s0s += __shfl_xor_sync(0xffffffffu, s0s, 2);
            s1s += __shfl_xor_sync(0xffffffffu, s1s, 1);
            s1s += __shfl_xor_sync(0xffffffffu, s1s, 2);
            l0 = l0 * corr0 + s0s;
            l1 = l1 * corr1 + s1s;

#pragma unroll
            for (int nt = 0; nt < 16; nt++) {
                acc_o[nt][0] *= corr0; acc_o[nt][1] *= corr0;
                acc_o[nt][2] *= corr1; acc_o[nt][3] *= corr1;
            }

            // ---- O += P @ V (shuffle transpose + paired LDS.128) ----
#pragma unroll
            for (int c = 0; c < 8; c++) {
                const int src0 = (lane & ~3) | (t >> 1);
                const int src2 = src0 + 2;
                const float e00 = __shfl_sync(0xffffffffu, accs[c][0], src0);
                const float e01 = __shfl_sync(0xffffffffu, accs[c][1], src0);
                const float e10 = __shfl_sync(0xffffffffu, accs[c][2], src0);
                const float e11 = __shfl_sync(0xffffffffu, accs[c][3], src0);
                const float f00 = __shfl_sync(0xffffffffu, accs[c][0], src2);
                const float f01 = __shfl_sync(0xffffffffu, accs[c][1], src2);
                const float f10 = __shfl_sync(0xffffffffu, accs[c][2], src2);
                const float f11 = __shfl_sync(0xffffffffu, accs[c][3], src2);
                const uint32_t a0 = f2tf32((t & 1) ? e01 : e00);
                const uint32_t a1 = f2tf32((t & 1) ? e11 : e10);
                const uint32_t a2 = f2tf32((t & 1) ? f01 : f00);
                const uint32_t a3 = f2tf32((t & 1) ? f11 : f10);
#pragma unroll
                for (int ntp = 0; ntp < 8; ntp++) {
                    uint4 bb = *(const uint4*)&Vf[((c * 8 + ntp) * 32 + lane) * 4];
                    mma_tf32(acc_o[2 * ntp],     a0, a1, a2, a3, bb.x, bb.y);
                    mma_tf32(acc_o[2 * ntp + 1], a0, a1, a2, a3, bb.z, bb.w);
                }
            }
        }

        CP_WAIT0();
        __syncthreads();
        if (ti + 1 < ntiles) {
            kv_convert(sm, wid & 7, lane);
            __syncthreads();
            if (ti + 2 < ntiles)
                kv_issue(raw_addr, kp + (size_t)(ti + 2) * 64 * 128,
                         vp + (size_t)(ti + 2) * 64 * 128, tid);
        }
    }

    // ---- epilogue: normalize + write g_attn as tf32 bits ----
    const float inv0 = 1.0f / l0;
    const float inv1 = 1.0f / l1;
    uint32_t* o = g_attn;
    const size_t ro0 = ((size_t)(b * T_ + r0)) * C_ + h * D_;
    const size_t ro1 = ((size_t)(b * T_ + r1)) * C_ + h * D_;
#pragma unroll
    for (int nt = 0; nt < 16; nt++) {
        const int col = nt * 8 + 2 * t;
        uint2 w0, w1;
        w0.x = f2tf32(acc_o[nt][0] * inv0); w0.y = f2tf32(acc_o[nt][1] * inv0);
        w1.x = f2tf32(acc_o[nt][2] * inv1); w1.y = f2tf32(acc_o[nt][3] * inv1);
        *(uint2*)&o[ro0 + col] = w0;
        *(uint2*)&o[ro1 + col] = w1;
    }
}

// ---------------------------------------------------------------------------
extern "C" void kernel_launch(void* const* d_in, const int* in_sizes, int n_in,
                              void* d_out, int out_size)
{
    const float* x  = (const float*)d_in[0];
    const float* wq = (const float*)d_in[1];
    const float* bq = (const float*)d_in[2];
    const float* wk = (const float*)d_in[3];
    const float* bk = (const float*)d_in[4];
    const float* wv = (const float*)d_in[5];
    const float* bv = (const float*)d_in[6];
    const float* wo = (const float*)d_in[7];

    float* out_main = (float*)d_out;                    // [B,T,C]
    float* out_k = out_main + (size_t)B_ * T_ * C_;     // [B,KV,T,D]
    float* out_v = out_k + (size_t)B_ * KV_ * T_ * D_;  // [B,KV,T,D]

    const int M = B_ * T_;  // 4096

    cudaFuncSetAttribute(qkv_gemm,
                         cudaFuncAttributeMaxDynamicSharedMemorySize, GEMM_SMEM_BYTES);
    cudaFuncSetAttribute(oproj_gemm,
                         cudaFuncAttributeMaxDynamicSharedMemorySize, GEMM_SMEM_BYTES);
    cudaFuncSetAttribute(flash_mma,
                         cudaFuncAttributeMaxDynamicSharedMemorySize, FL_SMEM_BYTES);

    // Pre-convert x + weights to tf32 bits
    {
        const int blocks = (N4_TOTAL + 255) / 256;
        cvt_all<<<blocks, 256>>>(x, wq, wk, wv, wo);
    }

    // Fused QKV projection (cp.async pipelined)
    {
        dim3 g(24, M / 128);
        qkv_gemm<<<g, 128, GEMM_SMEM_BYTES>>>(bq, bk, bv, out_k, out_v);
    }

    // RoPE on q (g_q) and k (out_k)
    {
        const int total = PQ + PK;
        rope_all<<<(total + 255) / 256, 256>>>(out_k);
    }

    // Flash attention
    {
        dim3 g(T_ / 128, H_, B_);
        flash_mma<<<g, 256, FL_SMEM_BYTES>>>(out_k, out_v);
    }

    // Output projection (A = g_attn tf32)
    {
        dim3 go(C_ / 128, M / 128);
        oproj_gemm<<<go, 128, GEMM_SMEM_BYTES>>>(out_main);
    }
}